// round 1
// baseline (speedup 1.0000x reference)
#include <cuda_runtime.h>

#define N_NODES 100000
#define N_EDGES 1600000
#define IN_DIM  256
#define OUT_DIM 64
#define NEG_SLOPE 0.01f

#define BM 128
#define BK 32
#define SCAN_B 512
#define SCAN_NB 196   // 196*512 = 100352 >= N_NODES

// ---------------- scratch (device globals; no allocations allowed) ----------
__device__ float g_z[N_NODES * OUT_DIM];
__device__ float g_ssrc[N_NODES];
__device__ float g_sdst[N_NODES];
__device__ float g_e[N_EDGES];
__device__ float g_ex[N_EDGES];
__device__ int   g_src[N_EDGES];
__device__ int   g_dst[N_EDGES];
__device__ float g_emax[N_NODES];
__device__ float g_denom[N_NODES];
__device__ int   g_cnt[N_NODES];
__device__ int   g_off[N_NODES];
__device__ int   g_cur[N_NODES];
__device__ int   g_perm[N_EDGES];
__device__ int   g_flag;
__device__ int   g_bsum[SCAN_NB];

// ---------------- helpers ----------------------------------------------------
__device__ __forceinline__ unsigned long long fma2(unsigned long long a,
                                                   unsigned long long b,
                                                   unsigned long long c) {
    unsigned long long d;
    asm("fma.rn.f32x2 %0, %1, %2, %3;" : "=l"(d) : "l"(a), "l"(b), "l"(c));
    return d;
}
__device__ __forceinline__ unsigned long long pack2(float x, float y) {
    unsigned long long r;
    asm("mov.b64 %0, {%1, %2};" : "=l"(r) : "f"(x), "f"(y));
    return r;
}
__device__ __forceinline__ float2 unpack2(unsigned long long v) {
    float2 f;
    asm("mov.b64 {%0, %1}, %2;" : "=f"(f.x), "=f"(f.y) : "l"(v));
    return f;
}
__device__ __forceinline__ void atomicMaxFloat(float* addr, float v) {
    if (v >= 0.0f) atomicMax((int*)addr, __float_as_int(v));
    else           atomicMin((unsigned int*)addr, (unsigned int)__float_as_int(v));
}

// ---------------- kernels -----------------------------------------------------
__global__ void k_init() {
    int i = blockIdx.x * blockDim.x + threadIdx.x;
    if (i < N_NODES) {
        g_emax[i]  = __int_as_float(0xff800000); // -inf
        g_denom[i] = 0.0f;
        g_cnt[i]   = 0;
    }
}

// Detect whether edge_index buffer is int64 or int32 (JAX canonicalization).
// Reading int32 data as int64 combines two random indices -> out of range.
__global__ void k_detect(const void* ei) {
    __shared__ int allok;
    if (threadIdx.x == 0) allok = 1;
    __syncthreads();
    const long long* p = (const long long*)ei;
    long long v = p[threadIdx.x];
    if (v < 0 || v >= N_NODES) allok = 0;
    __syncthreads();
    if (threadIdx.x == 0) g_flag = allok;
}

__global__ void k_convert(const void* ei) {
    int i = blockIdx.x * blockDim.x + threadIdx.x;
    if (i >= N_EDGES) return;
    int s, d;
    if (g_flag) {
        const long long* p = (const long long*)ei;
        s = (int)p[i];
        d = (int)p[N_EDGES + i];
    } else {
        const int* p = (const int*)ei;
        s = p[i];
        d = p[N_EDGES + i];
    }
    g_src[i] = s;
    g_dst[i] = d;
    atomicAdd(&g_cnt[d], 1);
}

// z = h @ W^T  (128-row x 64-col block tile, packed f32x2 FMA, 4 row-pairs x 4 cols/thread)
__global__ __launch_bounds__(256) void k_gemm(const float* __restrict__ h,
                                              const float* __restrict__ W) {
    __shared__ float As[BK][BM + 2];      // [k][row], stride 130 (8B-aligned rows)
    __shared__ float Ws[OUT_DIM][BK + 1]; // [col][k], stride 33 (conflict-free stores)

    int tid = threadIdx.x;
    int tx  = tid & 15;   // col group: cols tx*4 .. tx*4+3
    int ty  = tid >> 4;   // row group: rows ty*8 .. ty*8+7
    int r0  = blockIdx.x * BM;

    unsigned long long acc[4][4];
#pragma unroll
    for (int i = 0; i < 4; i++)
#pragma unroll
        for (int j = 0; j < 4; j++) acc[i][j] = 0ull;

    for (int kk = 0; kk < IN_DIM; kk += BK) {
        // A tile: 128x32 floats, 4 x float4 per thread, transposed into smem
#pragma unroll
        for (int jj = 0; jj < 4; jj++) {
            int idx = tid + jj * 256;
            int r = idx >> 3, q = idx & 7;
            float4 v = make_float4(0.f, 0.f, 0.f, 0.f);
            if (r0 + r < N_NODES)
                v = *(const float4*)&h[(r0 + r) * IN_DIM + kk + q * 4];
            As[q * 4 + 0][r] = v.x;
            As[q * 4 + 1][r] = v.y;
            As[q * 4 + 2][r] = v.z;
            As[q * 4 + 3][r] = v.w;
        }
        // W tile: 64x32 floats, 2 x float4 per thread
#pragma unroll
        for (int jj = 0; jj < 2; jj++) {
            int idx = tid + jj * 256;
            int c = idx >> 3, q = idx & 7;
            float4 v = *(const float4*)&W[c * IN_DIM + kk + q * 4];
            Ws[c][q * 4 + 0] = v.x;
            Ws[c][q * 4 + 1] = v.y;
            Ws[c][q * 4 + 2] = v.z;
            Ws[c][q * 4 + 3] = v.w;
        }
        __syncthreads();

#pragma unroll 8
        for (int k = 0; k < BK; k++) {
            unsigned long long hp[4];
#pragma unroll
            for (int i = 0; i < 4; i++)
                hp[i] = *(const unsigned long long*)&As[k][ty * 8 + i * 2];
#pragma unroll
            for (int j = 0; j < 4; j++) {
                float w = Ws[tx * 4 + j][k];
                unsigned long long ww = pack2(w, w);
#pragma unroll
                for (int i = 0; i < 4; i++)
                    acc[i][j] = fma2(hp[i], ww, acc[i][j]);
            }
        }
        __syncthreads();
    }

#pragma unroll
    for (int i = 0; i < 4; i++) {
        float2 p0 = unpack2(acc[i][0]);
        float2 p1 = unpack2(acc[i][1]);
        float2 p2 = unpack2(acc[i][2]);
        float2 p3 = unpack2(acc[i][3]);
        int r = r0 + ty * 8 + i * 2;
        if (r < N_NODES) {
            float4 lo = make_float4(p0.x, p1.x, p2.x, p3.x);
            *(float4*)&g_z[r * OUT_DIM + tx * 4] = lo;
        }
        if (r + 1 < N_NODES) {
            float4 hi = make_float4(p0.y, p1.y, p2.y, p3.y);
            *(float4*)&g_z[(r + 1) * OUT_DIM + tx * 4] = hi;
        }
    }
}

// s_src = z @ a_l, s_dst = z @ a_r
__global__ void k_scores(const float* __restrict__ a_attn) {
    __shared__ float al[OUT_DIM], ar[OUT_DIM];
    int tid = threadIdx.x;
    if (tid < OUT_DIM) {
        al[tid] = a_attn[tid];
        ar[tid] = a_attn[OUT_DIM + tid];
    }
    __syncthreads();
    int i = blockIdx.x * blockDim.x + tid;
    if (i >= N_NODES) return;
    const float4* zr = (const float4*)&g_z[i * OUT_DIM];
    float s0 = 0.f, s1 = 0.f;
#pragma unroll
    for (int q = 0; q < 16; q++) {
        float4 v = zr[q];
        s0 += v.x * al[q * 4] + v.y * al[q * 4 + 1] + v.z * al[q * 4 + 2] + v.w * al[q * 4 + 3];
        s1 += v.x * ar[q * 4] + v.y * ar[q * 4 + 1] + v.z * ar[q * 4 + 2] + v.w * ar[q * 4 + 3];
    }
    g_ssrc[i] = s0;
    g_sdst[i] = s1;
}

// e = leaky_relu(s_src[src] + s_dst[dst]); segment max by dst
__global__ void k_edge1() {
    int i = blockIdx.x * blockDim.x + threadIdx.x;
    if (i >= N_EDGES) return;
    int s = g_src[i], d = g_dst[i];
    float x = g_ssrc[s] + g_sdst[d];
    float e = x > 0.f ? x : NEG_SLOPE * x;
    g_e[i] = e;
    atomicMaxFloat(&g_emax[d], e);
}

// exclusive scan of counts -> offsets (3-phase)
__global__ void k_scan1() {
    __shared__ int sh[SCAN_B];
    int b = blockIdx.x, t = threadIdx.x;
    int i = b * SCAN_B + t;
    int v = (i < N_NODES) ? g_cnt[i] : 0;
    sh[t] = v;
    __syncthreads();
    for (int off = 1; off < SCAN_B; off <<= 1) {
        int x = (t >= off) ? sh[t - off] : 0;
        __syncthreads();
        sh[t] += x;
        __syncthreads();
    }
    if (i < N_NODES) g_off[i] = sh[t] - v;
    if (t == SCAN_B - 1) g_bsum[b] = sh[t];
}
__global__ void k_scan2() {
    int run = 0;
    for (int b = 0; b < SCAN_NB; b++) {
        int v = g_bsum[b];
        g_bsum[b] = run;
        run += v;
    }
}
__global__ void k_scan3() {
    int i = blockIdx.x * blockDim.x + threadIdx.x;
    if (i >= N_NODES) return;
    int o = g_off[i] + g_bsum[i / SCAN_B];
    g_off[i] = o;
    g_cur[i] = o;
}

// ex = exp(e - emax[dst]); denom += ex; CSR scatter of edge ids
__global__ void k_edge2() {
    int i = blockIdx.x * blockDim.x + threadIdx.x;
    if (i >= N_EDGES) return;
    int d = g_dst[i];
    float ex = __expf(g_e[i] - g_emax[d]);
    g_ex[i] = ex;
    atomicAdd(&g_denom[d], ex);
    int pos = atomicAdd(&g_cur[d], 1);
    g_perm[pos] = i;
}

// warp per node: h_out[d] = sum_e (ex_e/denom_d) * z[src_e]
__global__ void k_aggregate(float* __restrict__ out) {
    int w    = (blockIdx.x * blockDim.x + threadIdx.x) >> 5;
    int lane = threadIdx.x & 31;
    if (w >= N_NODES) return;
    int deg  = g_cnt[w];
    int base = g_off[w];
    float2 acc = make_float2(0.f, 0.f);
    if (deg > 0) {
        float inv = 1.f / g_denom[w];
        for (int j = 0; j < deg; j++) {
            int   eid = g_perm[base + j];
            float wt  = g_ex[eid] * inv;
            int   s   = g_src[eid];
            float2 v  = *(const float2*)&g_z[s * OUT_DIM + lane * 2];
            acc.x += wt * v.x;
            acc.y += wt * v.y;
        }
    }
    *(float2*)&out[w * OUT_DIM + lane * 2] = acc;
}

// ---------------- launch ------------------------------------------------------
extern "C" void kernel_launch(void* const* d_in, const int* in_sizes, int n_in,
                              void* d_out, int out_size) {
    const float* h = (const float*)d_in[0];
    const float* W = (const float*)d_in[1];
    const float* a = (const float*)d_in[2];
    const void*  ei = d_in[3];
    float* out = (float*)d_out;

    k_init<<<(N_NODES + 255) / 256, 256>>>();
    k_detect<<<1, 256>>>(ei);
    k_convert<<<(N_EDGES + 255) / 256, 256>>>(ei);
    k_gemm<<<(N_NODES + BM - 1) / BM, 256>>>(h, W);
    k_scores<<<(N_NODES + 255) / 256, 256>>>(a);
    k_edge1<<<(N_EDGES + 255) / 256, 256>>>();
    k_scan1<<<SCAN_NB, SCAN_B>>>();
    k_scan2<<<1, 1>>>();
    k_scan3<<<(N_NODES + 255) / 256, 256>>>();
    k_edge2<<<(N_EDGES + 255) / 256, 256>>>();
    k_aggregate<<<(N_NODES * 32 + 255) / 256, 256>>>(out);
}

// round 2
// speedup vs baseline: 1.1867x; 1.1867x over previous
#include <cuda_runtime.h>

#define N_NODES 100000
#define N_EDGES 1600000
#define IN_DIM  256
#define OUT_DIM 64
#define NEG_SLOPE 0.01f

#define BM 256
#define BK 32
#define SCAN_B 512
#define SCAN_NB 196   // 196*512 = 100352 >= N_NODES

// ---------------- scratch (device globals; no allocations allowed) ----------
__device__ float  g_z[N_NODES * OUT_DIM];
__device__ float  g_ssrc[N_NODES];
__device__ float  g_sdst[N_NODES];
__device__ int    g_src[N_EDGES];
__device__ int    g_dst[N_EDGES];
__device__ float2 g_edge[N_EDGES];     // (ex, src) in CSR order
__device__ int    g_cnt[N_NODES];
__device__ int    g_off[N_NODES];
__device__ int    g_cur[N_NODES];
__device__ int    g_flag;
__device__ int    g_bsum[SCAN_NB];
__device__ float  g_maxs[2];           // global max of s_src, s_dst

// ---------------- helpers ----------------------------------------------------
__device__ __forceinline__ unsigned long long fma2(unsigned long long a,
                                                   unsigned long long b,
                                                   unsigned long long c) {
    unsigned long long d;
    asm("fma.rn.f32x2 %0, %1, %2, %3;" : "=l"(d) : "l"(a), "l"(b), "l"(c));
    return d;
}
__device__ __forceinline__ unsigned long long pack2(float x, float y) {
    unsigned long long r;
    asm("mov.b64 %0, {%1, %2};" : "=l"(r) : "f"(x), "f"(y));
    return r;
}
__device__ __forceinline__ float2 unpack2(unsigned long long v) {
    float2 f;
    asm("mov.b64 {%0, %1}, %2;" : "=f"(f.x), "=f"(f.y) : "l"(v));
    return f;
}
__device__ __forceinline__ void atomicMaxFloat(float* addr, float v) {
    if (v >= 0.0f) atomicMax((int*)addr, __float_as_int(v));
    else           atomicMin((unsigned int*)addr, (unsigned int)__float_as_int(v));
}

// ---------------- kernels -----------------------------------------------------
__global__ void k_init() {
    int i = blockIdx.x * blockDim.x + threadIdx.x;
    if (i < N_NODES) g_cnt[i] = 0;
    if (i < 2) g_maxs[i] = __int_as_float(0xff800000);
}

// Detect int64 vs int32 edge_index (JAX canonicalization).
__global__ void k_detect(const void* ei) {
    __shared__ int allok;
    if (threadIdx.x == 0) allok = 1;
    __syncthreads();
    const long long* p = (const long long*)ei;
    long long v = p[threadIdx.x];
    if (v < 0 || v >= N_NODES) allok = 0;
    __syncthreads();
    if (threadIdx.x == 0) g_flag = allok;
}

__global__ void k_convert(const void* ei) {
    int i = blockIdx.x * blockDim.x + threadIdx.x;
    if (i >= N_EDGES) return;
    int s, d;
    if (g_flag) {
        const long long* p = (const long long*)ei;
        s = (int)p[i];
        d = (int)p[N_EDGES + i];
    } else {
        const int* p = (const int*)ei;
        s = p[i];
        d = p[N_EDGES + i];
    }
    g_src[i] = s;
    g_dst[i] = d;
    atomicAdd(&g_cnt[d], 1);
}

// z = h @ W^T. 256-row x 64-col tile; per thread 16 rows x 4 cols (32 fma2/k).
__global__ __launch_bounds__(256, 2) void k_gemm(const float* __restrict__ h,
                                                 const float* __restrict__ W) {
    __shared__ float As[BK][BM + 2];      // [k][row]
    __shared__ float Ws[OUT_DIM][BK + 1]; // [col][k]

    int tid = threadIdx.x;
    int tx  = tid & 15;   // cols tx*4 .. tx*4+3
    int ty  = tid >> 4;   // rows ty*16 .. ty*16+15
    int r0  = blockIdx.x * BM;

    unsigned long long acc[8][4];
#pragma unroll
    for (int i = 0; i < 8; i++)
#pragma unroll
        for (int j = 0; j < 4; j++) acc[i][j] = 0ull;

    for (int kk = 0; kk < IN_DIM; kk += BK) {
        // A tile: 256x32 floats, 8 x float4 per thread, transposed into smem
#pragma unroll
        for (int jj = 0; jj < 8; jj++) {
            int idx = tid + jj * 256;
            int r = idx >> 3, q = idx & 7;
            float4 v = make_float4(0.f, 0.f, 0.f, 0.f);
            if (r0 + r < N_NODES)
                v = *(const float4*)&h[(r0 + r) * IN_DIM + kk + q * 4];
            As[q * 4 + 0][r] = v.x;
            As[q * 4 + 1][r] = v.y;
            As[q * 4 + 2][r] = v.z;
            As[q * 4 + 3][r] = v.w;
        }
        // W tile: 64x32 floats, 2 x float4 per thread
#pragma unroll
        for (int jj = 0; jj < 2; jj++) {
            int idx = tid + jj * 256;
            int c = idx >> 3, q = idx & 7;
            float4 v = *(const float4*)&W[c * IN_DIM + kk + q * 4];
            Ws[c][q * 4 + 0] = v.x;
            Ws[c][q * 4 + 1] = v.y;
            Ws[c][q * 4 + 2] = v.z;
            Ws[c][q * 4 + 3] = v.w;
        }
        __syncthreads();

#pragma unroll 4
        for (int k = 0; k < BK; k++) {
            unsigned long long hp[8];
#pragma unroll
            for (int i = 0; i < 8; i++)
                hp[i] = *(const unsigned long long*)&As[k][ty * 16 + i * 2];
            unsigned long long ww[4];
#pragma unroll
            for (int j = 0; j < 4; j++) {
                float w = Ws[tx * 4 + j][k];
                ww[j] = pack2(w, w);
            }
#pragma unroll
            for (int j = 0; j < 4; j++)
#pragma unroll
                for (int i = 0; i < 8; i++)
                    acc[i][j] = fma2(hp[i], ww[j], acc[i][j]);
        }
        __syncthreads();
    }

#pragma unroll
    for (int i = 0; i < 8; i++) {
        float2 p0 = unpack2(acc[i][0]);
        float2 p1 = unpack2(acc[i][1]);
        float2 p2 = unpack2(acc[i][2]);
        float2 p3 = unpack2(acc[i][3]);
        int r = r0 + ty * 16 + i * 2;
        if (r < N_NODES)
            *(float4*)&g_z[r * OUT_DIM + tx * 4] = make_float4(p0.x, p1.x, p2.x, p3.x);
        if (r + 1 < N_NODES)
            *(float4*)&g_z[(r + 1) * OUT_DIM + tx * 4] = make_float4(p0.y, p1.y, p2.y, p3.y);
    }
}

// s_src = z @ a_l, s_dst = z @ a_r; also global max of each (for softmax shift)
__global__ void k_scores(const float* __restrict__ a_attn) {
    __shared__ float al[OUT_DIM], ar[OUT_DIM];
    __shared__ float m0s[8], m1s[8];
    int tid = threadIdx.x;
    if (tid < OUT_DIM) {
        al[tid] = a_attn[tid];
        ar[tid] = a_attn[OUT_DIM + tid];
    }
    __syncthreads();
    int i = blockIdx.x * blockDim.x + tid;
    float s0 = __int_as_float(0xff800000), s1 = s0;
    if (i < N_NODES) {
        const float4* zr = (const float4*)&g_z[i * OUT_DIM];
        s0 = 0.f; s1 = 0.f;
#pragma unroll
        for (int q = 0; q < 16; q++) {
            float4 v = zr[q];
            s0 += v.x * al[q*4] + v.y * al[q*4+1] + v.z * al[q*4+2] + v.w * al[q*4+3];
            s1 += v.x * ar[q*4] + v.y * ar[q*4+1] + v.z * ar[q*4+2] + v.w * ar[q*4+3];
        }
        g_ssrc[i] = s0;
        g_sdst[i] = s1;
    }
    // block max reduce
    float m0 = s0, m1 = s1;
#pragma unroll
    for (int o = 16; o > 0; o >>= 1) {
        m0 = fmaxf(m0, __shfl_xor_sync(0xffffffff, m0, o));
        m1 = fmaxf(m1, __shfl_xor_sync(0xffffffff, m1, o));
    }
    int wid = tid >> 5;
    if ((tid & 31) == 0) { m0s[wid] = m0; m1s[wid] = m1; }
    __syncthreads();
    if (tid == 0) {
        for (int w = 1; w < 8; w++) { m0 = fmaxf(m0, m0s[w]); m1 = fmaxf(m1, m1s[w]); }
        atomicMaxFloat(&g_maxs[0], m0);
        atomicMaxFloat(&g_maxs[1], m1);
    }
}

// exclusive scan of counts -> offsets
__global__ void k_scan1() {
    __shared__ int sh[SCAN_B];
    int b = blockIdx.x, t = threadIdx.x;
    int i = b * SCAN_B + t;
    int v = (i < N_NODES) ? g_cnt[i] : 0;
    sh[t] = v;
    __syncthreads();
    for (int off = 1; off < SCAN_B; off <<= 1) {
        int x = (t >= off) ? sh[t - off] : 0;
        __syncthreads();
        sh[t] += x;
        __syncthreads();
    }
    if (i < N_NODES) g_off[i] = sh[t] - v;
    if (t == SCAN_B - 1) g_bsum[b] = sh[t];
}
__global__ void k_scan2() {   // block scan over 196 partials (was serial!)
    __shared__ int sh[256];
    int t = threadIdx.x;
    int v = (t < SCAN_NB) ? g_bsum[t] : 0;
    sh[t] = v;
    __syncthreads();
    for (int off = 1; off < 256; off <<= 1) {
        int x = (t >= off) ? sh[t - off] : 0;
        __syncthreads();
        sh[t] += x;
        __syncthreads();
    }
    if (t < SCAN_NB) g_bsum[t] = sh[t] - v;  // exclusive
}
__global__ void k_scan3() {
    int i = blockIdx.x * blockDim.x + threadIdx.x;
    if (i >= N_NODES) return;
    int o = g_off[i] + g_bsum[i / SCAN_B];
    g_off[i] = o;
    g_cur[i] = o;
}

// e = lrelu(ssrc[s]+sdst[d]); ex = exp(e - M); scatter (ex, src) into CSR slot
__global__ void k_edge_fused() {
    int i = blockIdx.x * blockDim.x + threadIdx.x;
    if (i >= N_EDGES) return;
    float M = g_maxs[0] + g_maxs[1];   // constant shift: cancels exactly in alpha
    int s = g_src[i], d = g_dst[i];
    float x = g_ssrc[s] + g_sdst[d];
    float e = x > 0.f ? x : NEG_SLOPE * x;
    float ex = __expf(e - M);
    int pos = atomicAdd(&g_cur[d], 1);
    g_edge[pos] = make_float2(ex, __int_as_float(s));
}

// warp per node, 2 edges per iteration (half-warp x float4 each).
// denom is accumulated inline (wsum), so no atomic denom pass exists.
__global__ void k_aggregate(float* __restrict__ out) {
    int w    = (blockIdx.x * blockDim.x + threadIdx.x) >> 5;
    int lane = threadIdx.x & 31;
    if (w >= N_NODES) return;
    int deg  = g_cnt[w];
    int base = g_off[w];
    int half = lane >> 4;
    int col  = lane & 15;

    float4 acc = make_float4(0.f, 0.f, 0.f, 0.f);
    float  wsum = 0.f;

    int j = 0;
#pragma unroll 4
    for (; j + 2 <= deg; j += 2) {
        float2 ed = g_edge[base + j + half];
        float ex = ed.x;
        int   s  = __float_as_int(ed.y);
        float4 v = *(const float4*)&g_z[s * OUT_DIM + col * 4];
        acc.x += ex * v.x; acc.y += ex * v.y;
        acc.z += ex * v.z; acc.w += ex * v.w;
        wsum += ex;
    }
    if (j < deg && half == 0) {   // odd tail: half 0 only
        float2 ed = g_edge[base + j];
        float ex = ed.x;
        int   s  = __float_as_int(ed.y);
        float4 v = *(const float4*)&g_z[s * OUT_DIM + col * 4];
        acc.x += ex * v.x; acc.y += ex * v.y;
        acc.z += ex * v.z; acc.w += ex * v.w;
        wsum += ex;
    }
    // combine halves
    acc.x += __shfl_xor_sync(0xffffffff, acc.x, 16);
    acc.y += __shfl_xor_sync(0xffffffff, acc.y, 16);
    acc.z += __shfl_xor_sync(0xffffffff, acc.z, 16);
    acc.w += __shfl_xor_sync(0xffffffff, acc.w, 16);
    wsum  += __shfl_xor_sync(0xffffffff, wsum, 16);

    if (half == 0) {
        float inv = wsum > 0.f ? 1.f / wsum : 0.f;
        *(float4*)&out[w * OUT_DIM + col * 4] =
            make_float4(acc.x * inv, acc.y * inv, acc.z * inv, acc.w * inv);
    }
}

// ---------------- launch ------------------------------------------------------
extern "C" void kernel_launch(void* const* d_in, const int* in_sizes, int n_in,
                              void* d_out, int out_size) {
    const float* h = (const float*)d_in[0];
    const float* W = (const float*)d_in[1];
    const float* a = (const float*)d_in[2];
    const void*  ei = d_in[3];
    float* out = (float*)d_out;

    k_init<<<(N_NODES + 255) / 256, 256>>>();
    k_detect<<<1, 256>>>(ei);
    k_convert<<<(N_EDGES + 255) / 256, 256>>>(ei);
    k_gemm<<<(N_NODES + BM - 1) / BM, 256>>>(h, W);
    k_scores<<<(N_NODES + 255) / 256, 256>>>(a);
    k_scan1<<<SCAN_NB, SCAN_B>>>();
    k_scan2<<<1, 256>>>();
    k_scan3<<<(N_NODES + 255) / 256, 256>>>();
    k_edge_fused<<<(N_EDGES + 255) / 256, 256>>>();
    k_aggregate<<<(N_NODES * 32 + 255) / 256, 256>>>(out);
}

// round 4
// speedup vs baseline: 1.6434x; 1.3848x over previous
#include <cuda_runtime.h>
#include <cuda_bf16.h>
#include <cstdint>

#define N_NODES 100000
#define N_EDGES 1600000
#define IN_DIM  256
#define OUT_DIM 64
#define NEG_SLOPE 0.01f

#define SCAN_B 512
#define SCAN_NB 196   // 196*512 = 100352 >= N_NODES

// SMEM map for k_gemm_tc (dynamic): bf16 hi/lo tiles, SW128-swizzled rows of 128B
#define OFF_AHI 0
#define OFF_ALO 16384
#define OFF_BHI 32768
#define OFF_BLO 40960
#define OFF_ATT 49152
#define OFF_SS0 49664
#define OFF_SS1 50176
#define SMEM_TC_TOTAL 50688   // -> 2 CTAs/SM

// ---------------- scratch (device globals; no allocations allowed) ----------
__device__ float  g_z[N_NODES * OUT_DIM];
__device__ float  g_ssrc[N_NODES];
__device__ float  g_sdst[N_NODES];
__device__ int    g_src[N_EDGES];
__device__ int    g_dst[N_EDGES];
__device__ float2 g_edge[N_EDGES];     // (ex, src) in CSR order
__device__ int    g_cnt[N_NODES];
__device__ int    g_off[N_NODES];
__device__ int    g_cur[N_NODES];
__device__ int    g_flag;
__device__ int    g_bsum[SCAN_NB];
__device__ float  g_maxs[2];           // global max of s_src, s_dst

// ---------------- helpers ------------------------------------------------------
__device__ __forceinline__ uint32_t smem_to_u32(const void* p) {
    uint32_t a;
    asm("{ .reg .u64 t; cvta.to.shared.u64 t, %1; cvt.u32.u64 %0, t; }"
        : "=r"(a) : "l"(p));
    return a;
}
__device__ __forceinline__ uint32_t swzoff(int row, int colb) {
    uint32_t b = (uint32_t)(row * 128 + colb);
    return b ^ ((b >> 3) & 0x70);
}
// pack two floats -> bf16x2 (a in low 16 bits = lower address = even k)
__device__ __forceinline__ uint32_t pack_bf16(float a, float b) {
    uint32_t r;
    asm("{ .reg .b16 l, h;\n\t"
        "cvt.rn.bf16.f32 l, %1;\n\t"
        "cvt.rn.bf16.f32 h, %2;\n\t"
        "mov.b32 %0, {l, h}; }" : "=r"(r) : "f"(a), "f"(b));
    return r;
}
__device__ __forceinline__ float bf16lo_f(uint32_t v) { return __uint_as_float(v << 16); }
__device__ __forceinline__ float bf16hi_f(uint32_t v) { return __uint_as_float(v & 0xffff0000u); }

// 8 floats (one 16B bf16 granule) -> hi + lo uint4
__device__ __forceinline__ void cvt_granule(const float4& p, const float4& q,
                                            uint4& hi, uint4& lo) {
    hi.x = pack_bf16(p.x, p.y);
    hi.y = pack_bf16(p.z, p.w);
    hi.z = pack_bf16(q.x, q.y);
    hi.w = pack_bf16(q.z, q.w);
    lo.x = pack_bf16(p.x - bf16lo_f(hi.x), p.y - bf16hi_f(hi.x));
    lo.y = pack_bf16(p.z - bf16lo_f(hi.y), p.w - bf16hi_f(hi.y));
    lo.z = pack_bf16(q.x - bf16lo_f(hi.z), q.y - bf16hi_f(hi.z));
    lo.w = pack_bf16(q.z - bf16lo_f(hi.w), q.w - bf16hi_f(hi.w));
}
__device__ __forceinline__ uint4 ldsm4(uint32_t addr) {
    uint4 r;
    asm volatile("ldmatrix.sync.aligned.m8n8.x4.shared.b16 {%0,%1,%2,%3}, [%4];"
        : "=r"(r.x), "=r"(r.y), "=r"(r.z), "=r"(r.w) : "r"(addr));
    return r;
}
__device__ __forceinline__ void mma_bf16(float* d, const uint4& A, uint32_t b0, uint32_t b1) {
    asm volatile("mma.sync.aligned.m16n8k16.row.col.f32.bf16.bf16.f32 "
        "{%0,%1,%2,%3}, {%4,%5,%6,%7}, {%8,%9}, {%0,%1,%2,%3};"
        : "+f"(d[0]), "+f"(d[1]), "+f"(d[2]), "+f"(d[3])
        : "r"(A.x), "r"(A.y), "r"(A.z), "r"(A.w), "r"(b0), "r"(b1));
}
__device__ __forceinline__ void atomicMaxFloat(float* addr, float v) {
    if (v >= 0.0f) atomicMax((int*)addr, __float_as_int(v));
    else           atomicMin((unsigned int*)addr, (unsigned int)__float_as_int(v));
}

// ---------------- kernels -------------------------------------------------------
__global__ void k_init() {
    int i = blockIdx.x * blockDim.x + threadIdx.x;
    if (i < N_NODES) g_cnt[i] = 0;
    if (i < 2) g_maxs[i] = __int_as_float(0xff800000);
}

__global__ void k_detect(const void* ei) {
    __shared__ int allok;
    if (threadIdx.x == 0) allok = 1;
    __syncthreads();
    const long long* p = (const long long*)ei;
    long long v = p[threadIdx.x];
    if (v < 0 || v >= N_NODES) allok = 0;
    __syncthreads();
    if (threadIdx.x == 0) g_flag = allok;
}

__global__ void k_convert(const void* ei) {
    int i = blockIdx.x * blockDim.x + threadIdx.x;
    if (i >= N_EDGES) return;
    int s, d;
    if (g_flag) {
        const long long* p = (const long long*)ei;
        s = (int)p[i];
        d = (int)p[N_EDGES + i];
    } else {
        const int* p = (const int*)ei;
        s = p[i];
        d = p[N_EDGES + i];
    }
    g_src[i] = s;
    g_dst[i] = d;
    atomicAdd(&g_cnt[d], 1);
}

// z = h @ W^T via mma.sync bf16 3-term split (hi*hi + lo*hi + hi*lo), err ~1e-5.
// CTA: 128 rows x 64 cols, 8 warps in 4x2 (wr: m32, wc: n32). K chunks of 64.
// Fused epilogue: z write + attention scores + global max.
__global__ __launch_bounds__(256, 2) void k_gemm_tc(const float* __restrict__ h,
                                                    const float* __restrict__ W,
                                                    const float* __restrict__ a_attn) {
    extern __shared__ char smem[];
    const uint32_t sb = smem_to_u32(smem);
    const int tid = threadIdx.x, lane = tid & 31, wid = tid >> 5;
    const int wr = wid & 3, wc = wid >> 2;
    const int r0 = blockIdx.x * 128;

    float* sS0 = (float*)(smem + OFF_SS0);
    float* sS1 = (float*)(smem + OFF_SS1);
    if (tid < 128) {
        ((float*)(smem + OFF_ATT))[tid] = a_attn[tid];
        sS0[tid] = 0.f;
        sS1[tid] = 0.f;
    }

    float acc[2][4][4];
#pragma unroll
    for (int a = 0; a < 2; a++)
#pragma unroll
        for (int b = 0; b < 4; b++)
#pragma unroll
            for (int c = 0; c < 4; c++) acc[a][b][c] = 0.f;

    for (int it = 0; it < 4; it++) {
        const int k0 = it * 64;
        // stage global loads (A: 4 granules/thread, B: 2 granules/thread)
        float4 fa[4][2];
#pragma unroll
        for (int j = 0; j < 4; j++) {
            int g = tid + j * 256;
            int row = g >> 3, c8 = g & 7;
            int gr = r0 + row;
            if (gr < N_NODES) {
                fa[j][0] = *(const float4*)&h[gr * IN_DIM + k0 + c8 * 8];
                fa[j][1] = *(const float4*)&h[gr * IN_DIM + k0 + c8 * 8 + 4];
            } else {
                fa[j][0] = make_float4(0.f, 0.f, 0.f, 0.f);
                fa[j][1] = make_float4(0.f, 0.f, 0.f, 0.f);
            }
        }
        float4 fb[2][2];
#pragma unroll
        for (int j = 0; j < 2; j++) {
            int g = tid + j * 256;
            int row = g >> 3, c8 = g & 7;
            fb[j][0] = *(const float4*)&W[row * IN_DIM + k0 + c8 * 8];
            fb[j][1] = *(const float4*)&W[row * IN_DIM + k0 + c8 * 8 + 4];
        }

        __syncthreads();   // previous chunk fully consumed

#pragma unroll
        for (int j = 0; j < 4; j++) {
            int g = tid + j * 256;
            int row = g >> 3, c8 = g & 7;
            uint4 hi, lo;
            cvt_granule(fa[j][0], fa[j][1], hi, lo);
            uint32_t off = swzoff(row, c8 * 16);
            *(uint4*)(smem + OFF_AHI + off) = hi;
            *(uint4*)(smem + OFF_ALO + off) = lo;
        }
#pragma unroll
        for (int j = 0; j < 2; j++) {
            int g = tid + j * 256;
            int row = g >> 3, c8 = g & 7;
            uint4 hi, lo;
            cvt_granule(fb[j][0], fb[j][1], hi, lo);
            uint32_t off = swzoff(row, c8 * 16);
            *(uint4*)(smem + OFF_BHI + off) = hi;
            *(uint4*)(smem + OFF_BLO + off) = lo;
        }
        __syncthreads();

#pragma unroll
        for (int ks = 0; ks < 4; ks++) {
            uint4 Ah[2], Al[2], Bh[2], Bl[2];
            int arow  = wr * 32 + (lane & 15);
            int acolb = ks * 32 + ((lane >> 4) << 4);
#pragma unroll
            for (int mt = 0; mt < 2; mt++) {
                uint32_t ad = sb + OFF_AHI + swzoff(arow + mt * 16, acolb);
                Ah[mt] = ldsm4(ad);
                Al[mt] = ldsm4(ad + (OFF_ALO - OFF_AHI));
            }
            int brow  = wc * 32 + (lane & 7) + ((lane >> 4) << 3);
            int bcolb = ks * 32 + (((lane >> 3) & 1) << 4);
#pragma unroll
            for (int nb = 0; nb < 2; nb++) {
                uint32_t bd = sb + OFF_BHI + swzoff(brow + nb * 16, bcolb);
                Bh[nb] = ldsm4(bd);
                Bl[nb] = ldsm4(bd + (OFF_BLO - OFF_BHI));
            }
#pragma unroll
            for (int mt = 0; mt < 2; mt++)
#pragma unroll
                for (int nb = 0; nb < 2; nb++) {
                    mma_bf16(acc[mt][nb * 2],     Ah[mt], Bh[nb].x, Bh[nb].y);
                    mma_bf16(acc[mt][nb * 2 + 1], Ah[mt], Bh[nb].z, Bh[nb].w);
                    mma_bf16(acc[mt][nb * 2],     Al[mt], Bh[nb].x, Bh[nb].y);
                    mma_bf16(acc[mt][nb * 2 + 1], Al[mt], Bh[nb].z, Bh[nb].w);
                    mma_bf16(acc[mt][nb * 2],     Ah[mt], Bl[nb].x, Bl[nb].y);
                    mma_bf16(acc[mt][nb * 2 + 1], Ah[mt], Bl[nb].z, Bl[nb].w);
                }
        }
    }

    // Epilogue: write z, partial attention dots, cross-warp reduce via smem
    const float* al = (const float*)(smem + OFF_ATT);
    const float* ar = al + OUT_DIM;
#pragma unroll
    for (int mt = 0; mt < 2; mt++) {
#pragma unroll
        for (int half = 0; half < 2; half++) {
            int lr = wr * 32 + mt * 16 + (lane >> 2) + half * 8;
            int grow = r0 + lr;
            float s0 = 0.f, s1 = 0.f;
#pragma unroll
            for (int nt = 0; nt < 4; nt++) {
                int c = wc * 32 + nt * 8 + (lane & 3) * 2;
                float v0 = acc[mt][nt][half * 2];
                float v1 = acc[mt][nt][half * 2 + 1];
                s0 += v0 * al[c] + v1 * al[c + 1];
                s1 += v0 * ar[c] + v1 * ar[c + 1];
                if (grow < N_NODES)
                    *(float2*)&g_z[grow * OUT_DIM + c] = make_float2(v0, v1);
            }
            s0 += __shfl_xor_sync(0xffffffff, s0, 1);
            s0 += __shfl_xor_sync(0xffffffff, s0, 2);
            s1 += __shfl_xor_sync(0xffffffff, s1, 1);
            s1 += __shfl_xor_sync(0xffffffff, s1, 2);
            if ((lane & 3) == 0) {
                atomicAdd(&sS0[lr], s0);
                atomicAdd(&sS1[lr], s1);
            }
        }
    }
    __syncthreads();
    if (tid < 128) {
        int grow = r0 + tid;
        float s0 = sS0[tid], s1 = sS1[tid];
        if (grow < N_NODES) {
            g_ssrc[grow] = s0;
            g_sdst[grow] = s1;
        } else {
            s0 = __int_as_float(0xff800000);
            s1 = __int_as_float(0xff800000);
        }
#pragma unroll
        for (int o = 16; o > 0; o >>= 1) {
            s0 = fmaxf(s0, __shfl_xor_sync(0xffffffff, s0, o));
            s1 = fmaxf(s1, __shfl_xor_sync(0xffffffff, s1, o));
        }
        if ((tid & 31) == 0) {
            atomicMaxFloat(&g_maxs[0], s0);
            atomicMaxFloat(&g_maxs[1], s1);
        }
    }
}

// exclusive scan of counts -> offsets
__global__ void k_scan1() {
    __shared__ int sh[SCAN_B];
    int b = blockIdx.x, t = threadIdx.x;
    int i = b * SCAN_B + t;
    int v = (i < N_NODES) ? g_cnt[i] : 0;
    sh[t] = v;
    __syncthreads();
    for (int off = 1; off < SCAN_B; off <<= 1) {
        int x = (t >= off) ? sh[t - off] : 0;
        __syncthreads();
        sh[t] += x;
        __syncthreads();
    }
    if (i < N_NODES) g_off[i] = sh[t] - v;
    if (t == SCAN_B - 1) g_bsum[b] = sh[t];
}
__global__ void k_scan2() {
    __shared__ int sh[256];
    int t = threadIdx.x;
    int v = (t < SCAN_NB) ? g_bsum[t] : 0;
    sh[t] = v;
    __syncthreads();
    for (int off = 1; off < 256; off <<= 1) {
        int x = (t >= off) ? sh[t - off] : 0;
        __syncthreads();
        sh[t] += x;
        __syncthreads();
    }
    if (t < SCAN_NB) g_bsum[t] = sh[t] - v;
}
__global__ void k_scan3() {
    int i = blockIdx.x * blockDim.x + threadIdx.x;
    if (i >= N_NODES) return;
    int o = g_off[i] + g_bsum[i / SCAN_B];
    g_off[i] = o;
    g_cur[i] = o;
}

// e = lrelu(ssrc[s]+sdst[d]); ex = exp(e - M); scatter (ex, src) into CSR slot
__global__ void k_edge_fused() {
    int i = blockIdx.x * blockDim.x + threadIdx.x;
    if (i >= N_EDGES) return;
    float M = g_maxs[0] + g_maxs[1];
    int s = g_src[i], d = g_dst[i];
    float x = g_ssrc[s] + g_sdst[d];
    float e = x > 0.f ? x : NEG_SLOPE * x;
    float ex = __expf(e - M);
    int pos = atomicAdd(&g_cur[d], 1);
    g_edge[pos] = make_float2(ex, __int_as_float(s));
}

// warp per node, 2 edges per iteration (half-warp x float4 each)
__global__ void k_aggregate(float* __restrict__ out) {
    int w    = (blockIdx.x * blockDim.x + threadIdx.x) >> 5;
    int lane = threadIdx.x & 31;
    if (w >= N_NODES) return;
    int deg  = g_cnt[w];
    int base = g_off[w];
    int half = lane >> 4;
    int col  = lane & 15;

    float4 acc = make_float4(0.f, 0.f, 0.f, 0.f);
    float  wsum = 0.f;

    int j = 0;
#pragma unroll 4
    for (; j + 2 <= deg; j += 2) {
        float2 ed = g_edge[base + j + half];
        float ex = ed.x;
        int   s  = __float_as_int(ed.y);
        float4 v = *(const float4*)&g_z[s * OUT_DIM + col * 4];
        acc.x += ex * v.x; acc.y += ex * v.y;
        acc.z += ex * v.z; acc.w += ex * v.w;
        wsum += ex;
    }
    if (j < deg && half == 0) {
        float2 ed = g_edge[base + j];
        float ex = ed.x;
        int   s  = __float_as_int(ed.y);
        float4 v = *(const float4*)&g_z[s * OUT_DIM + col * 4];
        acc.x += ex * v.x; acc.y += ex * v.y;
        acc.z += ex * v.z; acc.w += ex * v.w;
        wsum += ex;
    }
    acc.x += __shfl_xor_sync(0xffffffff, acc.x, 16);
    acc.y += __shfl_xor_sync(0xffffffff, acc.y, 16);
    acc.z += __shfl_xor_sync(0xffffffff, acc.z, 16);
    acc.w += __shfl_xor_sync(0xffffffff, acc.w, 16);
    wsum  += __shfl_xor_sync(0xffffffff, wsum, 16);

    if (half == 0) {
        float inv = wsum > 0.f ? 1.f / wsum : 0.f;
        *(float4*)&out[w * OUT_DIM + col * 4] =
            make_float4(acc.x * inv, acc.y * inv, acc.z * inv, acc.w * inv);
    }
}

// ---------------- launch --------------------------------------------------------
extern "C" void kernel_launch(void* const* d_in, const int* in_sizes, int n_in,
                              void* d_out, int out_size) {
    const float* h = (const float*)d_in[0];
    const float* W = (const float*)d_in[1];
    const float* a = (const float*)d_in[2];
    const void*  ei = d_in[3];
    float* out = (float*)d_out;

    cudaFuncSetAttribute(k_gemm_tc, cudaFuncAttributeMaxDynamicSharedMemorySize, SMEM_TC_TOTAL);

    k_init<<<(N_NODES + 255) / 256, 256>>>();
    k_detect<<<1, 256>>>(ei);
    k_convert<<<(N_EDGES + 255) / 256, 256>>>(ei);
    k_gemm_tc<<<(N_NODES + 127) / 128, 256, SMEM_TC_TOTAL>>>(h, W, a);
    k_scan1<<<SCAN_NB, SCAN_B>>>();
    k_scan2<<<1, 256>>>();
    k_scan3<<<(N_NODES + 255) / 256, 256>>>();
    k_edge_fused<<<(N_EDGES + 255) / 256, 256>>>();
    k_aggregate<<<(N_NODES * 32 + 255) / 256, 256>>>(out);
}

// round 5
// speedup vs baseline: 1.6907x; 1.0288x over previous
#include <cuda_runtime.h>
#include <cuda_bf16.h>
#include <cuda_fp16.h>
#include <cstdint>

#define N_NODES 100000
#define N_EDGES 1600000
#define IN_DIM  256
#define OUT_DIM 64
#define NEG_SLOPE 0.01f

#define SCAN_B 512
#define SCAN_NB 196   // 196*512 = 100352 >= N_NODES

// SMEM map for k_gemm_tc (dynamic): bf16 hi/lo tiles, SW128-swizzled rows of 128B
#define OFF_AHI 0
#define OFF_ALO 16384
#define OFF_BHI 32768
#define OFF_BLO 40960
#define OFF_ATT 49152
#define OFF_SS0 49664
#define OFF_SS1 50176
#define SMEM_TC_TOTAL 50688   // -> 2 CTAs/SM

// ---------------- scratch (device globals; no allocations allowed) ----------
__device__ __half  g_zh[N_NODES * OUT_DIM];   // z in fp16 (aggregation operand)
__device__ float   g_ssrc[N_NODES];
__device__ float   g_sdst[N_NODES];
__device__ int2    g_sd[N_EDGES];             // (src, dst)
__device__ float2  g_edge[N_EDGES];           // (ex, src) in CSR order
__device__ int     g_cnt[N_NODES];
__device__ int     g_off[N_NODES];
__device__ int     g_cur[N_NODES];
__device__ int     g_flag;
__device__ int     g_bsum[SCAN_NB];
__device__ float   g_maxs[2];                 // global max of s_src, s_dst

// ---------------- helpers ------------------------------------------------------
__device__ __forceinline__ uint32_t smem_to_u32(const void* p) {
    uint32_t a;
    asm("{ .reg .u64 t; cvta.to.shared.u64 t, %1; cvt.u32.u64 %0, t; }"
        : "=r"(a) : "l"(p));
    return a;
}
__device__ __forceinline__ uint32_t swzoff(int row, int colb) {
    uint32_t b = (uint32_t)(row * 128 + colb);
    return b ^ ((b >> 3) & 0x70);
}
__device__ __forceinline__ uint32_t pack_bf16(float a, float b) {
    uint32_t r;
    asm("{ .reg .b16 l, h;\n\t"
        "cvt.rn.bf16.f32 l, %1;\n\t"
        "cvt.rn.bf16.f32 h, %2;\n\t"
        "mov.b32 %0, {l, h}; }" : "=r"(r) : "f"(a), "f"(b));
    return r;
}
__device__ __forceinline__ float bf16lo_f(uint32_t v) { return __uint_as_float(v << 16); }
__device__ __forceinline__ float bf16hi_f(uint32_t v) { return __uint_as_float(v & 0xffff0000u); }

__device__ __forceinline__ void cvt_granule(const float4& p, const float4& q,
                                            uint4& hi, uint4& lo) {
    hi.x = pack_bf16(p.x, p.y);
    hi.y = pack_bf16(p.z, p.w);
    hi.z = pack_bf16(q.x, q.y);
    hi.w = pack_bf16(q.z, q.w);
    lo.x = pack_bf16(p.x - bf16lo_f(hi.x), p.y - bf16hi_f(hi.x));
    lo.y = pack_bf16(p.z - bf16lo_f(hi.y), p.w - bf16hi_f(hi.y));
    lo.z = pack_bf16(q.x - bf16lo_f(hi.z), q.y - bf16hi_f(hi.z));
    lo.w = pack_bf16(q.z - bf16lo_f(hi.w), q.w - bf16hi_f(hi.w));
}
__device__ __forceinline__ uint4 ldsm4(uint32_t addr) {
    uint4 r;
    asm volatile("ldmatrix.sync.aligned.m8n8.x4.shared.b16 {%0,%1,%2,%3}, [%4];"
        : "=r"(r.x), "=r"(r.y), "=r"(r.z), "=r"(r.w) : "r"(addr));
    return r;
}
__device__ __forceinline__ void mma_bf16(float* d, const uint4& A, uint32_t b0, uint32_t b1) {
    asm volatile("mma.sync.aligned.m16n8k16.row.col.f32.bf16.bf16.f32 "
        "{%0,%1,%2,%3}, {%4,%5,%6,%7}, {%8,%9}, {%0,%1,%2,%3};"
        : "+f"(d[0]), "+f"(d[1]), "+f"(d[2]), "+f"(d[3])
        : "r"(A.x), "r"(A.y), "r"(A.z), "r"(A.w), "r"(b0), "r"(b1));
}
__device__ __forceinline__ void atomicMaxFloat(float* addr, float v) {
    if (v >= 0.0f) atomicMax((int*)addr, __float_as_int(v));
    else           atomicMin((unsigned int*)addr, (unsigned int)__float_as_int(v));
}

// ---------------- kernels -------------------------------------------------------
__global__ void k_detect(const void* ei) {
    __shared__ int allok;
    if (threadIdx.x == 0) allok = 1;
    __syncthreads();
    const long long* p = (const long long*)ei;
    long long v = p[threadIdx.x];
    if (v < 0 || v >= N_NODES) allok = 0;
    __syncthreads();
    if (threadIdx.x == 0) g_flag = allok;
}

__global__ void k_convert(const void* ei) {
    int i = blockIdx.x * blockDim.x + threadIdx.x;
    if (i >= N_EDGES) return;
    int s, d;
    if (g_flag) {
        const long long* p = (const long long*)ei;
        s = (int)p[i];
        d = (int)p[N_EDGES + i];
    } else {
        const int* p = (const int*)ei;
        s = p[i];
        d = p[N_EDGES + i];
    }
    g_sd[i] = make_int2(s, d);
    atomicAdd(&g_cnt[d], 1);
}

// z = h @ W^T via mma.sync bf16 3-term split. Epilogue: z(fp16) + scores + global max.
__global__ __launch_bounds__(256, 2) void k_gemm_tc(const float* __restrict__ h,
                                                    const float* __restrict__ W,
                                                    const float* __restrict__ a_attn) {
    extern __shared__ char smem[];
    const uint32_t sb = smem_to_u32(smem);
    const int tid = threadIdx.x, lane = tid & 31, wid = tid >> 5;
    const int wr = wid & 3, wc = wid >> 2;
    const int r0 = blockIdx.x * 128;

    float* sS0 = (float*)(smem + OFF_SS0);
    float* sS1 = (float*)(smem + OFF_SS1);
    if (tid < 128) {
        ((float*)(smem + OFF_ATT))[tid] = a_attn[tid];
        sS0[tid] = 0.f;
        sS1[tid] = 0.f;
    }

    float acc[2][4][4];
#pragma unroll
    for (int a = 0; a < 2; a++)
#pragma unroll
        for (int b = 0; b < 4; b++)
#pragma unroll
            for (int c = 0; c < 4; c++) acc[a][b][c] = 0.f;

    for (int it = 0; it < 4; it++) {
        const int k0 = it * 64;
        float4 fa[4][2];
#pragma unroll
        for (int j = 0; j < 4; j++) {
            int g = tid + j * 256;
            int row = g >> 3, c8 = g & 7;
            int gr = r0 + row;
            if (gr < N_NODES) {
                fa[j][0] = *(const float4*)&h[gr * IN_DIM + k0 + c8 * 8];
                fa[j][1] = *(const float4*)&h[gr * IN_DIM + k0 + c8 * 8 + 4];
            } else {
                fa[j][0] = make_float4(0.f, 0.f, 0.f, 0.f);
                fa[j][1] = make_float4(0.f, 0.f, 0.f, 0.f);
            }
        }
        float4 fb[2][2];
#pragma unroll
        for (int j = 0; j < 2; j++) {
            int g = tid + j * 256;
            int row = g >> 3, c8 = g & 7;
            fb[j][0] = *(const float4*)&W[row * IN_DIM + k0 + c8 * 8];
            fb[j][1] = *(const float4*)&W[row * IN_DIM + k0 + c8 * 8 + 4];
        }

        __syncthreads();

#pragma unroll
        for (int j = 0; j < 4; j++) {
            int g = tid + j * 256;
            int row = g >> 3, c8 = g & 7;
            uint4 hi, lo;
            cvt_granule(fa[j][0], fa[j][1], hi, lo);
            uint32_t off = swzoff(row, c8 * 16);
            *(uint4*)(smem + OFF_AHI + off) = hi;
            *(uint4*)(smem + OFF_ALO + off) = lo;
        }
#pragma unroll
        for (int j = 0; j < 2; j++) {
            int g = tid + j * 256;
            int row = g >> 3, c8 = g & 7;
            uint4 hi, lo;
            cvt_granule(fb[j][0], fb[j][1], hi, lo);
            uint32_t off = swzoff(row, c8 * 16);
            *(uint4*)(smem + OFF_BHI + off) = hi;
            *(uint4*)(smem + OFF_BLO + off) = lo;
        }
        __syncthreads();

#pragma unroll
        for (int ks = 0; ks < 4; ks++) {
            uint4 Ah[2], Al[2], Bh[2], Bl[2];
            int arow  = wr * 32 + (lane & 15);
            int acolb = ks * 32 + ((lane >> 4) << 4);
#pragma unroll
            for (int mt = 0; mt < 2; mt++) {
                uint32_t ad = sb + OFF_AHI + swzoff(arow + mt * 16, acolb);
                Ah[mt] = ldsm4(ad);
                Al[mt] = ldsm4(ad + (OFF_ALO - OFF_AHI));
            }
            int brow  = wc * 32 + (lane & 7) + ((lane >> 4) << 3);
            int bcolb = ks * 32 + (((lane >> 3) & 1) << 4);
#pragma unroll
            for (int nb = 0; nb < 2; nb++) {
                uint32_t bd = sb + OFF_BHI + swzoff(brow + nb * 16, bcolb);
                Bh[nb] = ldsm4(bd);
                Bl[nb] = ldsm4(bd + (OFF_BLO - OFF_BHI));
            }
#pragma unroll
            for (int mt = 0; mt < 2; mt++)
#pragma unroll
                for (int nb = 0; nb < 2; nb++) {
                    mma_bf16(acc[mt][nb * 2],     Ah[mt], Bh[nb].x, Bh[nb].y);
                    mma_bf16(acc[mt][nb * 2 + 1], Ah[mt], Bh[nb].z, Bh[nb].w);
                    mma_bf16(acc[mt][nb * 2],     Al[mt], Bh[nb].x, Bh[nb].y);
                    mma_bf16(acc[mt][nb * 2 + 1], Al[mt], Bh[nb].z, Bh[nb].w);
                    mma_bf16(acc[mt][nb * 2],     Ah[mt], Bl[nb].x, Bl[nb].y);
                    mma_bf16(acc[mt][nb * 2 + 1], Ah[mt], Bl[nb].z, Bl[nb].w);
                }
        }
    }

    // Epilogue: z (fp16) + attention score partials + cross-warp reduce
    const float* al = (const float*)(smem + OFF_ATT);
    const float* ar = al + OUT_DIM;
#pragma unroll
    for (int mt = 0; mt < 2; mt++) {
#pragma unroll
        for (int half = 0; half < 2; half++) {
            int lr = wr * 32 + mt * 16 + (lane >> 2) + half * 8;
            int grow = r0 + lr;
            float s0 = 0.f, s1 = 0.f;
#pragma unroll
            for (int nt = 0; nt < 4; nt++) {
                int c = wc * 32 + nt * 8 + (lane & 3) * 2;
                float v0 = acc[mt][nt][half * 2];
                float v1 = acc[mt][nt][half * 2 + 1];
                s0 += v0 * al[c] + v1 * al[c + 1];
                s1 += v0 * ar[c] + v1 * ar[c + 1];
                if (grow < N_NODES)
                    *(__half2*)&g_zh[grow * OUT_DIM + c] = __floats2half2_rn(v0, v1);
            }
            s0 += __shfl_xor_sync(0xffffffff, s0, 1);
            s0 += __shfl_xor_sync(0xffffffff, s0, 2);
            s1 += __shfl_xor_sync(0xffffffff, s1, 1);
            s1 += __shfl_xor_sync(0xffffffff, s1, 2);
            if ((lane & 3) == 0) {
                atomicAdd(&sS0[lr], s0);
                atomicAdd(&sS1[lr], s1);
            }
        }
    }
    __syncthreads();
    if (tid < 128) {
        int grow = r0 + tid;
        float s0 = sS0[tid], s1 = sS1[tid];
        if (grow < N_NODES) {
            g_ssrc[grow] = s0;
            g_sdst[grow] = s1;
        } else {
            s0 = __int_as_float(0xff800000);
            s1 = __int_as_float(0xff800000);
        }
#pragma unroll
        for (int o = 16; o > 0; o >>= 1) {
            s0 = fmaxf(s0, __shfl_xor_sync(0xffffffff, s0, o));
            s1 = fmaxf(s1, __shfl_xor_sync(0xffffffff, s1, o));
        }
        if ((tid & 31) == 0) {
            atomicMaxFloat(&g_maxs[0], s0);
            atomicMaxFloat(&g_maxs[1], s1);
        }
    }
}

// exclusive scan of counts -> offsets
__global__ void k_scan1() {
    __shared__ int sh[SCAN_B];
    int b = blockIdx.x, t = threadIdx.x;
    int i = b * SCAN_B + t;
    int v = (i < N_NODES) ? g_cnt[i] : 0;
    sh[t] = v;
    __syncthreads();
    for (int off = 1; off < SCAN_B; off <<= 1) {
        int x = (t >= off) ? sh[t - off] : 0;
        __syncthreads();
        sh[t] += x;
        __syncthreads();
    }
    if (i < N_NODES) g_off[i] = sh[t] - v;
    if (t == SCAN_B - 1) g_bsum[b] = sh[t];
}
__global__ void k_scan2() {
    __shared__ int sh[256];
    int t = threadIdx.x;
    int v = (t < SCAN_NB) ? g_bsum[t] : 0;
    sh[t] = v;
    __syncthreads();
    for (int off = 1; off < 256; off <<= 1) {
        int x = (t >= off) ? sh[t - off] : 0;
        __syncthreads();
        sh[t] += x;
        __syncthreads();
    }
    if (t < SCAN_NB) g_bsum[t] = sh[t] - v;
}
__global__ void k_scan3() {
    int i = blockIdx.x * blockDim.x + threadIdx.x;
    if (i >= N_NODES) return;
    int o = g_off[i] + g_bsum[i / SCAN_B];
    g_off[i] = o;
    g_cur[i] = o;
}

// e = lrelu(ssrc[s]+sdst[d]); ex = exp(e - M); scatter (ex, src) into CSR slot
__global__ void k_edge_fused() {
    int i = blockIdx.x * blockDim.x + threadIdx.x;
    if (i >= N_EDGES) return;
    float M = g_maxs[0] + g_maxs[1];
    int2 sd = g_sd[i];
    float x = g_ssrc[sd.x] + g_sdst[sd.y];
    float e = x > 0.f ? x : NEG_SLOPE * x;
    float ex = __expf(e - M);
    int pos = atomicAdd(&g_cur[sd.y], 1);
    g_edge[pos] = make_float2(ex, __int_as_float(sd.x));
}

// warp per node, quarter-warp per edge (8 lanes x 16B = 128B fp16 z row), 4 edges/iter
__global__ void k_aggregate(float* __restrict__ out) {
    int w    = (blockIdx.x * blockDim.x + threadIdx.x) >> 5;
    int lane = threadIdx.x & 31;
    if (w >= N_NODES) return;
    int deg  = g_cnt[w];
    int base = g_off[w];
    int q = lane >> 3;        // edge slot within group of 4
    int r = lane & 7;         // column octet: cols r*8 .. r*8+7

    float acc[8];
#pragma unroll
    for (int k = 0; k < 8; k++) acc[k] = 0.f;
    float wsum = 0.f;

    int j = 0;
    for (; j + 4 <= deg; j += 4) {
        float2 ed = g_edge[base + j + q];
        float ex = ed.x;
        int   s  = __float_as_int(ed.y);
        uint4 v = *(const uint4*)&g_zh[s * OUT_DIM + r * 8];
        float2 p0 = __half22float2(*(__half2*)&v.x);
        float2 p1 = __half22float2(*(__half2*)&v.y);
        float2 p2 = __half22float2(*(__half2*)&v.z);
        float2 p3 = __half22float2(*(__half2*)&v.w);
        acc[0] += ex * p0.x; acc[1] += ex * p0.y;
        acc[2] += ex * p1.x; acc[3] += ex * p1.y;
        acc[4] += ex * p2.x; acc[5] += ex * p2.y;
        acc[6] += ex * p3.x; acc[7] += ex * p3.y;
        wsum += ex;
    }
    int rem = deg - j;
    if (q < rem) {
        float2 ed = g_edge[base + j + q];
        float ex = ed.x;
        int   s  = __float_as_int(ed.y);
        uint4 v = *(const uint4*)&g_zh[s * OUT_DIM + r * 8];
        float2 p0 = __half22float2(*(__half2*)&v.x);
        float2 p1 = __half22float2(*(__half2*)&v.y);
        float2 p2 = __half22float2(*(__half2*)&v.z);
        float2 p3 = __half22float2(*(__half2*)&v.w);
        acc[0] += ex * p0.x; acc[1] += ex * p0.y;
        acc[2] += ex * p1.x; acc[3] += ex * p1.y;
        acc[4] += ex * p2.x; acc[5] += ex * p2.y;
        acc[6] += ex * p3.x; acc[7] += ex * p3.y;
        wsum += ex;
    }
    // combine the 4 quarter-warps (xor 8, then 16)
#pragma unroll
    for (int o = 8; o <= 16; o <<= 1) {
#pragma unroll
        for (int k = 0; k < 8; k++)
            acc[k] += __shfl_xor_sync(0xffffffff, acc[k], o);
        wsum += __shfl_xor_sync(0xffffffff, wsum, o);
    }
    if (q == 0) {
        float inv = wsum > 0.f ? 1.f / wsum : 0.f;
        *(float4*)&out[w * OUT_DIM + r * 8] =
            make_float4(acc[0] * inv, acc[1] * inv, acc[2] * inv, acc[3] * inv);
        *(float4*)&out[w * OUT_DIM + r * 8 + 4] =
            make_float4(acc[4] * inv, acc[5] * inv, acc[6] * inv, acc[7] * inv);
    }
}

// ---------------- launch --------------------------------------------------------
extern "C" void kernel_launch(void* const* d_in, const int* in_sizes, int n_in,
                              void* d_out, int out_size) {
    const float* h = (const float*)d_in[0];
    const float* W = (const float*)d_in[1];
    const float* a = (const float*)d_in[2];
    const void*  ei = d_in[3];
    float* out = (float*)d_out;

    cudaFuncSetAttribute(k_gemm_tc, cudaFuncAttributeMaxDynamicSharedMemorySize, SMEM_TC_TOTAL);

    void* p_cnt = nullptr;
    void* p_maxs = nullptr;
    cudaGetSymbolAddress(&p_cnt, g_cnt);
    cudaGetSymbolAddress(&p_maxs, g_maxs);
    cudaMemsetAsync(p_cnt, 0, N_NODES * sizeof(int));
    cudaMemsetAsync(p_maxs, 0xFF, 2 * sizeof(float));   // -NaN: identity for both atomic paths

    k_detect<<<1, 256>>>(ei);
    k_convert<<<(N_EDGES + 255) / 256, 256>>>(ei);
    k_gemm_tc<<<(N_NODES + 127) / 128, 256, SMEM_TC_TOTAL>>>(h, W, a);
    k_scan1<<<SCAN_NB, SCAN_B>>>();
    k_scan2<<<1, 256>>>();
    k_scan3<<<(N_NODES + 255) / 256, 256>>>();
    k_edge_fused<<<(N_EDGES + 255) / 256, 256>>>();
    k_aggregate<<<(N_NODES * 32 + 255) / 256, 256>>>(out);
}

// round 6
// speedup vs baseline: 1.7144x; 1.0140x over previous
#include <cuda_runtime.h>
#include <cuda_bf16.h>
#include <cuda_fp16.h>
#include <cstdint>

#define N_NODES 100000
#define N_EDGES 1600000
#define IN_DIM  256
#define OUT_DIM 64
#define NEG_SLOPE 0.01f

#define SCAN_B 512
#define SCAN_NB 196   // 196*512 = 100352 >= N_NODES

// SMEM map for k_gemm_tc: double-buffered bf16 hi/lo tiles (SW128 swizzle)
#define B_AHI 0
#define B_ALO 16384
#define B_BHI 32768
#define B_BLO 40960
#define BUF_SZ 49152
#define OFF_ATT 98304
#define OFF_SS0 98816
#define OFF_SS1 99328
#define SMEM_TC_TOTAL 99840   // 2 CTAs/SM (195KB of 228KB)

// ---------------- scratch (device globals; no allocations allowed) ----------
__device__ __half  g_zh[N_NODES * OUT_DIM];   // z in fp16 (aggregation operand)
__device__ float   g_ssrc[N_NODES];
__device__ float   g_sdst[N_NODES];
__device__ int2    g_sd[N_EDGES];             // (src, dst)
__device__ float2  g_edge[N_EDGES];           // (ex, src) in CSR order
__device__ int     g_cnt[N_NODES];
__device__ int     g_off[N_NODES];
__device__ int     g_cur[N_NODES];
__device__ int     g_flag;
__device__ int     g_bsum[SCAN_NB];
__device__ float   g_maxs[2];

// ---------------- helpers ------------------------------------------------------
__device__ __forceinline__ uint32_t smem_to_u32(const void* p) {
    uint32_t a;
    asm("{ .reg .u64 t; cvta.to.shared.u64 t, %1; cvt.u32.u64 %0, t; }"
        : "=r"(a) : "l"(p));
    return a;
}
__device__ __forceinline__ uint32_t swzoff(int row, int colb) {
    uint32_t b = (uint32_t)(row * 128 + colb);
    return b ^ ((b >> 3) & 0x70);
}
__device__ __forceinline__ uint32_t pack_bf16(float a, float b) {
    uint32_t r;
    asm("{ .reg .b16 l, h;\n\t"
        "cvt.rn.bf16.f32 l, %1;\n\t"
        "cvt.rn.bf16.f32 h, %2;\n\t"
        "mov.b32 %0, {l, h}; }" : "=r"(r) : "f"(a), "f"(b));
    return r;
}
__device__ __forceinline__ float bf16lo_f(uint32_t v) { return __uint_as_float(v << 16); }
__device__ __forceinline__ float bf16hi_f(uint32_t v) { return __uint_as_float(v & 0xffff0000u); }

__device__ __forceinline__ void cvt_granule(const float4& p, const float4& q,
                                            uint4& hi, uint4& lo) {
    hi.x = pack_bf16(p.x, p.y);
    hi.y = pack_bf16(p.z, p.w);
    hi.z = pack_bf16(q.x, q.y);
    hi.w = pack_bf16(q.z, q.w);
    lo.x = pack_bf16(p.x - bf16lo_f(hi.x), p.y - bf16hi_f(hi.x));
    lo.y = pack_bf16(p.z - bf16lo_f(hi.y), p.w - bf16hi_f(hi.y));
    lo.z = pack_bf16(q.x - bf16lo_f(hi.z), q.y - bf16hi_f(hi.z));
    lo.w = pack_bf16(q.z - bf16lo_f(hi.w), q.w - bf16hi_f(hi.w));
}
__device__ __forceinline__ uint4 ldsm4(uint32_t addr) {
    uint4 r;
    asm volatile("ldmatrix.sync.aligned.m8n8.x4.shared.b16 {%0,%1,%2,%3}, [%4];"
        : "=r"(r.x), "=r"(r.y), "=r"(r.z), "=r"(r.w) : "r"(addr));
    return r;
}
__device__ __forceinline__ void mma_bf16(float* d, const uint4& A, uint32_t b0, uint32_t b1) {
    asm volatile("mma.sync.aligned.m16n8k16.row.col.f32.bf16.bf16.f32 "
        "{%0,%1,%2,%3}, {%4,%5,%6,%7}, {%8,%9}, {%0,%1,%2,%3};"
        : "+f"(d[0]), "+f"(d[1]), "+f"(d[2]), "+f"(d[3])
        : "r"(A.x), "r"(A.y), "r"(A.z), "r"(A.w), "r"(b0), "r"(b1));
}
__device__ __forceinline__ void atomicMaxFloat(float* addr, float v) {
    if (v >= 0.0f) atomicMax((int*)addr, __float_as_int(v));
    else           atomicMin((unsigned int*)addr, (unsigned int)__float_as_int(v));
}

// ---- GEMM building blocks ----
__device__ __forceinline__ void ldg_chunk(const float* __restrict__ h,
                                          const float* __restrict__ W,
                                          int r0, int k0, int tid,
                                          float4 fa[4][2], float4 fb[2][2]) {
#pragma unroll
    for (int j = 0; j < 4; j++) {
        int g = tid + j * 256;
        int row = g >> 3, c8 = g & 7;
        int gr = r0 + row;
        if (gr < N_NODES) {
            fa[j][0] = *(const float4*)&h[gr * IN_DIM + k0 + c8 * 8];
            fa[j][1] = *(const float4*)&h[gr * IN_DIM + k0 + c8 * 8 + 4];
        } else {
            fa[j][0] = make_float4(0.f, 0.f, 0.f, 0.f);
            fa[j][1] = make_float4(0.f, 0.f, 0.f, 0.f);
        }
    }
#pragma unroll
    for (int j = 0; j < 2; j++) {
        int g = tid + j * 256;
        int row = g >> 3, c8 = g & 7;
        fb[j][0] = *(const float4*)&W[row * IN_DIM + k0 + c8 * 8];
        fb[j][1] = *(const float4*)&W[row * IN_DIM + k0 + c8 * 8 + 4];
    }
}

__device__ __forceinline__ void cvt_sts(char* smem, int bufbase, int tid,
                                        const float4 fa[4][2], const float4 fb[2][2]) {
#pragma unroll
    for (int j = 0; j < 4; j++) {
        int g = tid + j * 256;
        int row = g >> 3, c8 = g & 7;
        uint4 hi, lo;
        cvt_granule(fa[j][0], fa[j][1], hi, lo);
        uint32_t off = swzoff(row, c8 * 16);
        *(uint4*)(smem + bufbase + B_AHI + off) = hi;
        *(uint4*)(smem + bufbase + B_ALO + off) = lo;
    }
#pragma unroll
    for (int j = 0; j < 2; j++) {
        int g = tid + j * 256;
        int row = g >> 3, c8 = g & 7;
        uint4 hi, lo;
        cvt_granule(fb[j][0], fb[j][1], hi, lo);
        uint32_t off = swzoff(row, c8 * 16);
        *(uint4*)(smem + bufbase + B_BHI + off) = hi;
        *(uint4*)(smem + bufbase + B_BLO + off) = lo;
    }
}

__device__ __forceinline__ void mma_chunk(uint32_t sbuf, int wr, int wc, int lane,
                                          float acc[2][4][4]) {
#pragma unroll
    for (int ks = 0; ks < 4; ks++) {
        uint4 Ah[2], Al[2], Bh[2], Bl[2];
        int arow  = wr * 32 + (lane & 15);
        int acolb = ks * 32 + ((lane >> 4) << 4);
#pragma unroll
        for (int mt = 0; mt < 2; mt++) {
            uint32_t ad = sbuf + B_AHI + swzoff(arow + mt * 16, acolb);
            Ah[mt] = ldsm4(ad);
            Al[mt] = ldsm4(ad + (B_ALO - B_AHI));
        }
        int brow  = wc * 32 + (lane & 7) + ((lane >> 4) << 3);
        int bcolb = ks * 32 + (((lane >> 3) & 1) << 4);
#pragma unroll
        for (int nb = 0; nb < 2; nb++) {
            uint32_t bd = sbuf + B_BHI + swzoff(brow + nb * 16, bcolb);
            Bh[nb] = ldsm4(bd);
            Bl[nb] = ldsm4(bd + (B_BLO - B_BHI));
        }
#pragma unroll
        for (int mt = 0; mt < 2; mt++)
#pragma unroll
            for (int nb = 0; nb < 2; nb++) {
                mma_bf16(acc[mt][nb * 2],     Ah[mt], Bh[nb].x, Bh[nb].y);
                mma_bf16(acc[mt][nb * 2 + 1], Ah[mt], Bh[nb].z, Bh[nb].w);
                mma_bf16(acc[mt][nb * 2],     Al[mt], Bh[nb].x, Bh[nb].y);
                mma_bf16(acc[mt][nb * 2 + 1], Al[mt], Bh[nb].z, Bh[nb].w);
                mma_bf16(acc[mt][nb * 2],     Ah[mt], Bl[nb].x, Bl[nb].y);
                mma_bf16(acc[mt][nb * 2 + 1], Ah[mt], Bl[nb].z, Bl[nb].w);
            }
    }
}

// ---------------- kernels -------------------------------------------------------
__global__ void k_detect(const void* ei) {
    __shared__ int allok;
    if (threadIdx.x == 0) allok = 1;
    __syncthreads();
    const long long* p = (const long long*)ei;
    long long v = p[threadIdx.x];
    if (v < 0 || v >= N_NODES) allok = 0;
    __syncthreads();
    if (threadIdx.x == 0) g_flag = allok;
}

__global__ void k_convert(const void* ei) {
    int i = blockIdx.x * blockDim.x + threadIdx.x;
    if (i >= N_EDGES) return;
    int s, d;
    if (g_flag) {
        const long long* p = (const long long*)ei;
        s = (int)p[i];
        d = (int)p[N_EDGES + i];
    } else {
        const int* p = (const int*)ei;
        s = p[i];
        d = p[N_EDGES + i];
    }
    g_sd[i] = make_int2(s, d);
    atomicAdd(&g_cnt[d], 1);
}

// z = h @ W^T (bf16 3-term MMA, double-buffered smem pipeline).
// Epilogue: z(fp16) + attention scores + global max.
__global__ __launch_bounds__(256, 2) void k_gemm_tc(const float* __restrict__ h,
                                                    const float* __restrict__ W,
                                                    const float* __restrict__ a_attn) {
    extern __shared__ char smem[];
    const uint32_t sb = smem_to_u32(smem);
    const int tid = threadIdx.x, lane = tid & 31, wid = tid >> 5;
    const int wr = wid & 3, wc = wid >> 2;
    const int r0 = blockIdx.x * 128;

    float* sS0 = (float*)(smem + OFF_SS0);
    float* sS1 = (float*)(smem + OFF_SS1);
    if (tid < 128) {
        ((float*)(smem + OFF_ATT))[tid] = a_attn[tid];
        sS0[tid] = 0.f;
        sS1[tid] = 0.f;
    }

    float acc[2][4][4];
#pragma unroll
    for (int a = 0; a < 2; a++)
#pragma unroll
        for (int b = 0; b < 4; b++)
#pragma unroll
            for (int c = 0; c < 4; c++) acc[a][b][c] = 0.f;

    float4 fa[4][2], fb[2][2];

    // prologue: chunk 0 into buffer 0
    ldg_chunk(h, W, r0, 0, tid, fa, fb);
    cvt_sts(smem, 0, tid, fa, fb);
    __syncthreads();

#pragma unroll
    for (int it = 1; it < 4; it++) {
        ldg_chunk(h, W, r0, it * 64, tid, fa, fb);        // issue loads early
        mma_chunk(sb + ((it - 1) & 1) * BUF_SZ, wr, wc, lane, acc);  // hide LDG latency
        cvt_sts(smem, (it & 1) * BUF_SZ, tid, fa, fb);
        __syncthreads();
    }
    mma_chunk(sb + BUF_SZ, wr, wc, lane, acc);   // chunk 3 (buffer 1)

    // Epilogue: z (fp16) + attention score partials + cross-warp reduce
    const float* al = (const float*)(smem + OFF_ATT);
    const float* ar = al + OUT_DIM;
#pragma unroll
    for (int mt = 0; mt < 2; mt++) {
#pragma unroll
        for (int half = 0; half < 2; half++) {
            int lr = wr * 32 + mt * 16 + (lane >> 2) + half * 8;
            int grow = r0 + lr;
            float s0 = 0.f, s1 = 0.f;
#pragma unroll
            for (int nt = 0; nt < 4; nt++) {
                int c = wc * 32 + nt * 8 + (lane & 3) * 2;
                float v0 = acc[mt][nt][half * 2];
                float v1 = acc[mt][nt][half * 2 + 1];
                s0 += v0 * al[c] + v1 * al[c + 1];
                s1 += v0 * ar[c] + v1 * ar[c + 1];
                if (grow < N_NODES)
                    *(__half2*)&g_zh[grow * OUT_DIM + c] = __floats2half2_rn(v0, v1);
            }
            s0 += __shfl_xor_sync(0xffffffff, s0, 1);
            s0 += __shfl_xor_sync(0xffffffff, s0, 2);
            s1 += __shfl_xor_sync(0xffffffff, s1, 1);
            s1 += __shfl_xor_sync(0xffffffff, s1, 2);
            if ((lane & 3) == 0) {
                atomicAdd(&sS0[lr], s0);
                atomicAdd(&sS1[lr], s1);
            }
        }
    }
    __syncthreads();
    if (tid < 128) {
        int grow = r0 + tid;
        float s0 = sS0[tid], s1 = sS1[tid];
        if (grow < N_NODES) {
            g_ssrc[grow] = s0;
            g_sdst[grow] = s1;
        } else {
            s0 = __int_as_float(0xff800000);
            s1 = __int_as_float(0xff800000);
        }
#pragma unroll
        for (int o = 16; o > 0; o >>= 1) {
            s0 = fmaxf(s0, __shfl_xor_sync(0xffffffff, s0, o));
            s1 = fmaxf(s1, __shfl_xor_sync(0xffffffff, s1, o));
        }
        if ((tid & 31) == 0) {
            atomicMaxFloat(&g_maxs[0], s0);
            atomicMaxFloat(&g_maxs[1], s1);
        }
    }
}

// per-block exclusive scan via warp shuffles (2 syncs)
__global__ void k_scan1() {
    __shared__ int wsum[16];
    int b = blockIdx.x, t = threadIdx.x;
    int lane = t & 31, wid = t >> 5;
    int i = b * SCAN_B + t;
    int v = (i < N_NODES) ? g_cnt[i] : 0;
    int x = v;
#pragma unroll
    for (int o = 1; o < 32; o <<= 1) {
        int y = __shfl_up_sync(0xffffffff, x, o);
        if (lane >= o) x += y;
    }
    if (lane == 31) wsum[wid] = x;
    __syncthreads();
    if (wid == 0) {
        int s = (lane < 16) ? wsum[lane] : 0;
#pragma unroll
        for (int o = 1; o < 16; o <<= 1) {
            int y = __shfl_up_sync(0xffffffff, s, o);
            if (lane >= o) s += y;
        }
        if (lane < 16) wsum[lane] = s;
    }
    __syncthreads();
    int wb = wid ? wsum[wid - 1] : 0;
    int incl = wb + x;
    if (i < N_NODES) g_off[i] = incl - v;
    if (t == SCAN_B - 1) g_bsum[b] = incl;
}

// each block computes its own bsum prefix (reduction) and applies it
__global__ void k_scan23() {
    __shared__ int red[16];
    __shared__ int prefix;
    int b = blockIdx.x, t = threadIdx.x;
    int v = (t < b && t < SCAN_NB) ? g_bsum[t] : 0;
#pragma unroll
    for (int o = 16; o > 0; o >>= 1) v += __shfl_xor_sync(0xffffffff, v, o);
    if ((t & 31) == 0) red[t >> 5] = v;
    __syncthreads();
    if (t == 0) {
        int s = 0;
#pragma unroll
        for (int k = 0; k < 16; k++) s += red[k];
        prefix = s;
    }
    __syncthreads();
    int i = b * SCAN_B + t;
    if (i < N_NODES) {
        int o = g_off[i] + prefix;
        g_off[i] = o;
        g_cur[i] = o;
    }
}

// e = lrelu(ssrc[s]+sdst[d]); ex = exp(e - M); scatter (ex, src) into CSR slot
__global__ void k_edge_fused() {
    int i = blockIdx.x * blockDim.x + threadIdx.x;
    if (i >= N_EDGES) return;
    float M = g_maxs[0] + g_maxs[1];
    int2 sd = g_sd[i];
    float x = g_ssrc[sd.x] + g_sdst[sd.y];
    float e = x > 0.f ? x : NEG_SLOPE * x;
    float ex = __expf(e - M);
    int pos = atomicAdd(&g_cur[sd.y], 1);
    g_edge[pos] = make_float2(ex, __int_as_float(sd.x));
}

// warp per node, quarter-warp per edge, 8 edges in flight per iteration
__global__ void k_aggregate(float* __restrict__ out) {
    int w    = (blockIdx.x * blockDim.x + threadIdx.x) >> 5;
    int lane = threadIdx.x & 31;
    if (w >= N_NODES) return;
    int deg  = g_cnt[w];
    int base = g_off[w];
    int q = lane >> 3;        // edge slot within group of 4
    int r = lane & 7;         // column octet

    float acc[8];
#pragma unroll
    for (int k = 0; k < 8; k++) acc[k] = 0.f;
    float wsum = 0.f;

    int j = 0;
    for (; j + 8 <= deg; j += 8) {
        float2 e0 = g_edge[base + j + q];
        float2 e1 = g_edge[base + j + 4 + q];
        int s0 = __float_as_int(e0.y);
        int s1 = __float_as_int(e1.y);
        uint4 v0 = *(const uint4*)&g_zh[s0 * OUT_DIM + r * 8];
        uint4 v1 = *(const uint4*)&g_zh[s1 * OUT_DIM + r * 8];
        {
            float2 p0 = __half22float2(*(__half2*)&v0.x);
            float2 p1 = __half22float2(*(__half2*)&v0.y);
            float2 p2 = __half22float2(*(__half2*)&v0.z);
            float2 p3 = __half22float2(*(__half2*)&v0.w);
            acc[0] += e0.x * p0.x; acc[1] += e0.x * p0.y;
            acc[2] += e0.x * p1.x; acc[3] += e0.x * p1.y;
            acc[4] += e0.x * p2.x; acc[5] += e0.x * p2.y;
            acc[6] += e0.x * p3.x; acc[7] += e0.x * p3.y;
        }
        {
            float2 p0 = __half22float2(*(__half2*)&v1.x);
            float2 p1 = __half22float2(*(__half2*)&v1.y);
            float2 p2 = __half22float2(*(__half2*)&v1.z);
            float2 p3 = __half22float2(*(__half2*)&v1.w);
            acc[0] += e1.x * p0.x; acc[1] += e1.x * p0.y;
            acc[2] += e1.x * p1.x; acc[3] += e1.x * p1.y;
            acc[4] += e1.x * p2.x; acc[5] += e1.x * p2.y;
            acc[6] += e1.x * p3.x; acc[7] += e1.x * p3.y;
        }
        wsum += e0.x + e1.x;
    }
    if (j + 4 <= deg) {
        float2 ed = g_edge[base + j + q];
        int   s  = __float_as_int(ed.y);
        uint4 v = *(const uint4*)&g_zh[s * OUT_DIM + r * 8];
        float2 p0 = __half22float2(*(__half2*)&v.x);
        float2 p1 = __half22float2(*(__half2*)&v.y);
        float2 p2 = __half22float2(*(__half2*)&v.z);
        float2 p3 = __half22float2(*(__half2*)&v.w);
        acc[0] += ed.x * p0.x; acc[1] += ed.x * p0.y;
        acc[2] += ed.x * p1.x; acc[3] += ed.x * p1.y;
        acc[4] += ed.x * p2.x; acc[5] += ed.x * p2.y;
        acc[6] += ed.x * p3.x; acc[7] += ed.x * p3.y;
        wsum += ed.x;
        j += 4;
    }
    int rem = deg - j;
    if (q < rem) {
        float2 ed = g_edge[base + j + q];
        int   s  = __float_as_int(ed.y);
        uint4 v = *(const uint4*)&g_zh[s * OUT_DIM + r * 8];
        float2 p0 = __half22float2(*(__half2*)&v.x);
        float2 p1 = __half22float2(*(__half2*)&v.y);
        float2 p2 = __half22float2(*(__half2*)&v.z);
        float2 p3 = __half22float2(*(__half2*)&v.w);
        acc[0] += ed.x * p0.x; acc[1] += ed.x * p0.y;
        acc[2] += ed.x * p1.x; acc[3] += ed.x * p1.y;
        acc[4] += ed.x * p2.x; acc[5] += ed.x * p2.y;
        acc[6] += ed.x * p3.x; acc[7] += ed.x * p3.y;
        wsum += ed.x;
    }
#pragma unroll
    for (int o = 8; o <= 16; o <<= 1) {
#pragma unroll
        for (int k = 0; k < 8; k++)
            acc[k] += __shfl_xor_sync(0xffffffff, acc[k], o);
        wsum += __shfl_xor_sync(0xffffffff, wsum, o);
    }
    if (q == 0) {
        float inv = wsum > 0.f ? 1.f / wsum : 0.f;
        *(float4*)&out[w * OUT_DIM + r * 8] =
            make_float4(acc[0] * inv, acc[1] * inv, acc[2] * inv, acc[3] * inv);
        *(float4*)&out[w * OUT_DIM + r * 8 + 4] =
            make_float4(acc[4] * inv, acc[5] * inv, acc[6] * inv, acc[7] * inv);
    }
}

// ---------------- launch --------------------------------------------------------
extern "C" void kernel_launch(void* const* d_in, const int* in_sizes, int n_in,
                              void* d_out, int out_size) {
    const float* h = (const float*)d_in[0];
    const float* W = (const float*)d_in[1];
    const float* a = (const float*)d_in[2];
    const void*  ei = d_in[3];
    float* out = (float*)d_out;

    cudaFuncSetAttribute(k_gemm_tc, cudaFuncAttributeMaxDynamicSharedMemorySize, SMEM_TC_TOTAL);

    void* p_cnt = nullptr;
    void* p_maxs = nullptr;
    cudaGetSymbolAddress(&p_cnt, g_cnt);
    cudaGetSymbolAddress(&p_maxs, g_maxs);
    cudaMemsetAsync(p_cnt, 0, N_NODES * sizeof(int));
    cudaMemsetAsync(p_maxs, 0xFF, 2 * sizeof(float));   // -NaN: identity for both atomic paths

    k_detect<<<1, 256>>>(ei);
    k_convert<<<(N_EDGES + 255) / 256, 256>>>(ei);
    k_gemm_tc<<<(N_NODES + 127) / 128, 256, SMEM_TC_TOTAL>>>(h, W, a);
    k_scan1<<<SCAN_NB, SCAN_B>>>();
    k_scan23<<<SCAN_NB, SCAN_B>>>();
    k_edge_fused<<<(N_EDGES + 255) / 256, 256>>>();
    k_aggregate<<<(N_NODES * 32 + 255) / 256, 256>>>(out);
}

// round 7
// speedup vs baseline: 1.8034x; 1.0519x over previous
#include <cuda_runtime.h>
#include <cuda_bf16.h>
#include <cuda_fp16.h>
#include <cstdint>

#define N_NODES 100000
#define N_EDGES 1600000
#define IN_DIM  256
#define OUT_DIM 64
#define NEG_SLOPE 0.01f

#define SCAN_B 512
#define SCAN_NB 196   // 196*512 = 100352 >= N_NODES

#define NGB 782                         // gemm blocks (ceil(100000/128))
#define NCB ((N_EDGES + 1023) / 1024)   // convert blocks, 4 edges/thread

// SMEM map for fat kernel: double-buffered bf16 hi/lo tiles (SW128 swizzle)
#define B_AHI 0
#define B_ALO 16384
#define B_BHI 32768
#define B_BLO 40960
#define BUF_SZ 49152
#define OFF_ATT 98304
#define OFF_SS0 98816
#define OFF_SS1 99328
#define SMEM_TC_TOTAL 99840   // 2 CTAs/SM

// ---------------- scratch (device globals; no allocations allowed) ----------
__device__ __half  g_zh[N_NODES * OUT_DIM];
__device__ float   g_ssrc[N_NODES];
__device__ float   g_sdst[N_NODES];
__device__ int2    g_sd[N_EDGES];
__device__ float2  g_edge[N_EDGES];     // (ex, src) in CSR order
__device__ int     g_cnt[N_NODES];
__device__ int     g_off[N_NODES];
__device__ int     g_cur[N_NODES];
__device__ float   g_maxs[2];
__device__ unsigned long long g_scanstate[SCAN_NB];  // (value<<2)|flag; 0=empty,1=aggregate,2=inclusive

// ---------------- helpers ------------------------------------------------------
__device__ __forceinline__ uint32_t smem_to_u32(const void* p) {
    uint32_t a;
    asm("{ .reg .u64 t; cvta.to.shared.u64 t, %1; cvt.u32.u64 %0, t; }"
        : "=r"(a) : "l"(p));
    return a;
}
__device__ __forceinline__ uint32_t swzoff(int row, int colb) {
    uint32_t b = (uint32_t)(row * 128 + colb);
    return b ^ ((b >> 3) & 0x70);
}
__device__ __forceinline__ uint32_t pack_bf16(float a, float b) {
    uint32_t r;
    asm("{ .reg .b16 l, h;\n\t"
        "cvt.rn.bf16.f32 l, %1;\n\t"
        "cvt.rn.bf16.f32 h, %2;\n\t"
        "mov.b32 %0, {l, h}; }" : "=r"(r) : "f"(a), "f"(b));
    return r;
}
__device__ __forceinline__ float bf16lo_f(uint32_t v) { return __uint_as_float(v << 16); }
__device__ __forceinline__ float bf16hi_f(uint32_t v) { return __uint_as_float(v & 0xffff0000u); }

__device__ __forceinline__ void cvt_granule(const float4& p, const float4& q,
                                            uint4& hi, uint4& lo) {
    hi.x = pack_bf16(p.x, p.y);
    hi.y = pack_bf16(p.z, p.w);
    hi.z = pack_bf16(q.x, q.y);
    hi.w = pack_bf16(q.z, q.w);
    lo.x = pack_bf16(p.x - bf16lo_f(hi.x), p.y - bf16hi_f(hi.x));
    lo.y = pack_bf16(p.z - bf16lo_f(hi.y), p.w - bf16hi_f(hi.y));
    lo.z = pack_bf16(q.x - bf16lo_f(hi.z), q.y - bf16hi_f(hi.z));
    lo.w = pack_bf16(q.z - bf16lo_f(hi.w), q.w - bf16hi_f(hi.w));
}
__device__ __forceinline__ uint4 ldsm4(uint32_t addr) {
    uint4 r;
    asm volatile("ldmatrix.sync.aligned.m8n8.x4.shared.b16 {%0,%1,%2,%3}, [%4];"
        : "=r"(r.x), "=r"(r.y), "=r"(r.z), "=r"(r.w) : "r"(addr));
    return r;
}
__device__ __forceinline__ void mma_bf16(float* d, const uint4& A, uint32_t b0, uint32_t b1) {
    asm volatile("mma.sync.aligned.m16n8k16.row.col.f32.bf16.bf16.f32 "
        "{%0,%1,%2,%3}, {%4,%5,%6,%7}, {%8,%9}, {%0,%1,%2,%3};"
        : "+f"(d[0]), "+f"(d[1]), "+f"(d[2]), "+f"(d[3])
        : "r"(A.x), "r"(A.y), "r"(A.z), "r"(A.w), "r"(b0), "r"(b1));
}
__device__ __forceinline__ void atomicMaxFloat(float* addr, float v) {
    if (v >= 0.0f) atomicMax((int*)addr, __float_as_int(v));
    else           atomicMin((unsigned int*)addr, (unsigned int)__float_as_int(v));
}

// ---- GEMM building blocks ----
__device__ __forceinline__ void ldg_chunk(const float* __restrict__ h,
                                          const float* __restrict__ W,
                                          int r0, int k0, int tid,
                                          float4 fa[4][2], float4 fb[2][2]) {
#pragma unroll
    for (int j = 0; j < 4; j++) {
        int g = tid + j * 256;
        int row = g >> 3, c8 = g & 7;
        int gr = r0 + row;
        if (gr < N_NODES) {
            fa[j][0] = *(const float4*)&h[gr * IN_DIM + k0 + c8 * 8];
            fa[j][1] = *(const float4*)&h[gr * IN_DIM + k0 + c8 * 8 + 4];
        } else {
            fa[j][0] = make_float4(0.f, 0.f, 0.f, 0.f);
            fa[j][1] = make_float4(0.f, 0.f, 0.f, 0.f);
        }
    }
#pragma unroll
    for (int j = 0; j < 2; j++) {
        int g = tid + j * 256;
        int row = g >> 3, c8 = g & 7;
        fb[j][0] = *(const float4*)&W[row * IN_DIM + k0 + c8 * 8];
        fb[j][1] = *(const float4*)&W[row * IN_DIM + k0 + c8 * 8 + 4];
    }
}

__device__ __forceinline__ void cvt_sts(char* smem, int bufbase, int tid,
                                        const float4 fa[4][2], const float4 fb[2][2]) {
#pragma unroll
    for (int j = 0; j < 4; j++) {
        int g = tid + j * 256;
        int row = g >> 3, c8 = g & 7;
        uint4 hi, lo;
        cvt_granule(fa[j][0], fa[j][1], hi, lo);
        uint32_t off = swzoff(row, c8 * 16);
        *(uint4*)(smem + bufbase + B_AHI + off) = hi;
        *(uint4*)(smem + bufbase + B_ALO + off) = lo;
    }
#pragma unroll
    for (int j = 0; j < 2; j++) {
        int g = tid + j * 256;
        int row = g >> 3, c8 = g & 7;
        uint4 hi, lo;
        cvt_granule(fb[j][0], fb[j][1], hi, lo);
        uint32_t off = swzoff(row, c8 * 16);
        *(uint4*)(smem + bufbase + B_BHI + off) = hi;
        *(uint4*)(smem + bufbase + B_BLO + off) = lo;
    }
}

__device__ __forceinline__ void mma_chunk(uint32_t sbuf, int wr, int wc, int lane,
                                          float acc[2][4][4]) {
#pragma unroll
    for (int ks = 0; ks < 4; ks++) {
        uint4 Ah[2], Al[2], Bh[2], Bl[2];
        int arow  = wr * 32 + (lane & 15);
        int acolb = ks * 32 + ((lane >> 4) << 4);
#pragma unroll
        for (int mt = 0; mt < 2; mt++) {
            uint32_t ad = sbuf + B_AHI + swzoff(arow + mt * 16, acolb);
            Ah[mt] = ldsm4(ad);
            Al[mt] = ldsm4(ad + (B_ALO - B_AHI));
        }
        int brow  = wc * 32 + (lane & 7) + ((lane >> 4) << 3);
        int bcolb = ks * 32 + (((lane >> 3) & 1) << 4);
#pragma unroll
        for (int nb = 0; nb < 2; nb++) {
            uint32_t bd = sbuf + B_BHI + swzoff(brow + nb * 16, bcolb);
            Bh[nb] = ldsm4(bd);
            Bl[nb] = ldsm4(bd + (B_BLO - B_BHI));
        }
#pragma unroll
        for (int mt = 0; mt < 2; mt++)
#pragma unroll
            for (int nb = 0; nb < 2; nb++) {
                mma_bf16(acc[mt][nb * 2],     Ah[mt], Bh[nb].x, Bh[nb].y);
                mma_bf16(acc[mt][nb * 2 + 1], Ah[mt], Bh[nb].z, Bh[nb].w);
                mma_bf16(acc[mt][nb * 2],     Al[mt], Bh[nb].x, Bh[nb].y);
                mma_bf16(acc[mt][nb * 2 + 1], Al[mt], Bh[nb].z, Bh[nb].w);
                mma_bf16(acc[mt][nb * 2],     Ah[mt], Bl[nb].x, Bl[nb].y);
                mma_bf16(acc[mt][nb * 2 + 1], Ah[mt], Bl[nb].z, Bl[nb].w);
            }
    }
}

// ---------------- fat kernel: GEMM blocks [0, NGB) + convert blocks [NGB, NGB+NCB) ----
__global__ __launch_bounds__(256, 2) void k_fat(const float* __restrict__ h,
                                                const float* __restrict__ W,
                                                const float* __restrict__ a_attn,
                                                const void* __restrict__ ei) {
    extern __shared__ char smem[];
    const int bid = blockIdx.x;
    const int tid = threadIdx.x;

    if (bid >= NGB) {
        // ---------------- convert path: 1024 edges/block, 4/thread ----------------
        __shared__ int s_flag;
        if (tid < 32) {
            const long long* p = (const long long*)ei;
            long long v = p[tid];
            int ok = (v >= 0 && v < N_NODES);
            unsigned m = __ballot_sync(0xffffffff, ok);
            if (tid == 0) s_flag = (m == 0xffffffffu);
        }
        __syncthreads();
        int base = (bid - NGB) * 1024 + tid * 4;
        if (base + 3 >= N_EDGES) return;
        int s0, s1, s2, s3, d0, d1, d2, d3;
        if (s_flag) {
            const long long* p = (const long long*)ei;
            longlong2 a = *(const longlong2*)(p + base);
            longlong2 b = *(const longlong2*)(p + base + 2);
            longlong2 c = *(const longlong2*)(p + N_EDGES + base);
            longlong2 d = *(const longlong2*)(p + N_EDGES + base + 2);
            s0 = (int)a.x; s1 = (int)a.y; s2 = (int)b.x; s3 = (int)b.y;
            d0 = (int)c.x; d1 = (int)c.y; d2 = (int)d.x; d3 = (int)d.y;
        } else {
            const int* p = (const int*)ei;
            int4 a = *(const int4*)(p + base);
            int4 c = *(const int4*)(p + N_EDGES + base);
            s0 = a.x; s1 = a.y; s2 = a.z; s3 = a.w;
            d0 = c.x; d1 = c.y; d2 = c.z; d3 = c.w;
        }
        *(int4*)&g_sd[base]     = make_int4(s0, d0, s1, d1);
        *(int4*)&g_sd[base + 2] = make_int4(s2, d2, s3, d3);
        atomicAdd(&g_cnt[d0], 1);
        atomicAdd(&g_cnt[d1], 1);
        atomicAdd(&g_cnt[d2], 1);
        atomicAdd(&g_cnt[d3], 1);
        return;
    }

    // ---------------- GEMM path ----------------
    const uint32_t sb = smem_to_u32(smem);
    const int lane = tid & 31, wid = tid >> 5;
    const int wr = wid & 3, wc = wid >> 2;
    const int r0 = bid * 128;

    float* sS0 = (float*)(smem + OFF_SS0);
    float* sS1 = (float*)(smem + OFF_SS1);
    if (tid < 128) {
        ((float*)(smem + OFF_ATT))[tid] = a_attn[tid];
        sS0[tid] = 0.f;
        sS1[tid] = 0.f;
    }

    float acc[2][4][4];
#pragma unroll
    for (int a = 0; a < 2; a++)
#pragma unroll
        for (int b = 0; b < 4; b++)
#pragma unroll
            for (int c = 0; c < 4; c++) acc[a][b][c] = 0.f;

    float4 fa[4][2], fb[2][2];
    ldg_chunk(h, W, r0, 0, tid, fa, fb);
    cvt_sts(smem, 0, tid, fa, fb);
    __syncthreads();

#pragma unroll
    for (int it = 1; it < 4; it++) {
        ldg_chunk(h, W, r0, it * 64, tid, fa, fb);
        mma_chunk(sb + ((it - 1) & 1) * BUF_SZ, wr, wc, lane, acc);
        cvt_sts(smem, (it & 1) * BUF_SZ, tid, fa, fb);
        __syncthreads();
    }
    mma_chunk(sb + BUF_SZ, wr, wc, lane, acc);

    const float* al = (const float*)(smem + OFF_ATT);
    const float* ar = al + OUT_DIM;
#pragma unroll
    for (int mt = 0; mt < 2; mt++) {
#pragma unroll
        for (int half = 0; half < 2; half++) {
            int lr = wr * 32 + mt * 16 + (lane >> 2) + half * 8;
            int grow = r0 + lr;
            float s0 = 0.f, s1 = 0.f;
#pragma unroll
            for (int nt = 0; nt < 4; nt++) {
                int c = wc * 32 + nt * 8 + (lane & 3) * 2;
                float v0 = acc[mt][nt][half * 2];
                float v1 = acc[mt][nt][half * 2 + 1];
                s0 += v0 * al[c] + v1 * al[c + 1];
                s1 += v0 * ar[c] + v1 * ar[c + 1];
                if (grow < N_NODES)
                    *(__half2*)&g_zh[grow * OUT_DIM + c] = __floats2half2_rn(v0, v1);
            }
            s0 += __shfl_xor_sync(0xffffffff, s0, 1);
            s0 += __shfl_xor_sync(0xffffffff, s0, 2);
            s1 += __shfl_xor_sync(0xffffffff, s1, 1);
            s1 += __shfl_xor_sync(0xffffffff, s1, 2);
            if ((lane & 3) == 0) {
                atomicAdd(&sS0[lr], s0);
                atomicAdd(&sS1[lr], s1);
            }
        }
    }
    __syncthreads();
    if (tid < 128) {
        int grow = r0 + tid;
        float s0 = sS0[tid], s1 = sS1[tid];
        if (grow < N_NODES) {
            g_ssrc[grow] = s0;
            g_sdst[grow] = s1;
        } else {
            s0 = __int_as_float(0xff800000);
            s1 = __int_as_float(0xff800000);
        }
#pragma unroll
        for (int o = 16; o > 0; o >>= 1) {
            s0 = fmaxf(s0, __shfl_xor_sync(0xffffffff, s0, o));
            s1 = fmaxf(s1, __shfl_xor_sync(0xffffffff, s1, o));
        }
        if ((tid & 31) == 0) {
            atomicMaxFloat(&g_maxs[0], s0);
            atomicMaxFloat(&g_maxs[1], s1);
        }
    }
}

// ---------------- single-pass scan with decoupled lookback ----------------------
__global__ void k_scan() {
    __shared__ int wsum[16];
    __shared__ int s_prefix;
    const int b = blockIdx.x, t = threadIdx.x;
    const int lane = t & 31, wid = t >> 5;
    const int i = b * SCAN_B + t;
    int v = (i < N_NODES) ? g_cnt[i] : 0;

    // block-local inclusive scan (warp shuffles)
    int x = v;
#pragma unroll
    for (int o = 1; o < 32; o <<= 1) {
        int y = __shfl_up_sync(0xffffffff, x, o);
        if (lane >= o) x += y;
    }
    if (lane == 31) wsum[wid] = x;
    __syncthreads();
    if (wid == 0) {
        int s = (lane < 16) ? wsum[lane] : 0;
#pragma unroll
        for (int o = 1; o < 16; o <<= 1) {
            int y = __shfl_up_sync(0xffffffff, s, o);
            if (lane >= o) s += y;
        }
        if (lane < 16) wsum[lane] = s;
    }
    __syncthreads();
    int incl = (wid ? wsum[wid - 1] : 0) + x;

    // publish aggregate (block 0 publishes inclusive immediately)
    if (t == SCAN_B - 1) {
        unsigned long long pub = ((unsigned long long)incl << 2) | (b == 0 ? 2u : 1u);
        atomicExch(&g_scanstate[b], pub);
    }

    // warp-windowed lookback (warp 0)
    if (b > 0 && wid == 0) {
        long long run = 0;
        int j = b - 1;
        while (true) {
            int idx = j - lane;
            unsigned long long s;
            if (idx >= 0) {
                do { s = atomicAdd(&g_scanstate[idx], 0ull); } while ((s & 3) == 0);
            } else {
                s = 2ull;   // before block 0: inclusive 0
            }
            unsigned mask = __ballot_sync(0xffffffff, (s & 3) == 2);
            long long contrib;
            if (mask) {
                int fl = __ffs(mask) - 1;
                contrib = (lane <= fl) ? (long long)(s >> 2) : 0;
            } else {
                contrib = (long long)(s >> 2);
            }
#pragma unroll
            for (int o = 16; o > 0; o >>= 1)
                contrib += __shfl_xor_sync(0xffffffff, contrib, o);
            run += contrib;
            if (mask) break;
            j -= 32;
        }
        if (lane == 0) s_prefix = (int)run;
    } else if (t == 0) {
        s_prefix = 0;
    }
    __syncthreads();
    int prefix = s_prefix;

    if (b > 0 && t == SCAN_B - 1)
        atomicExch(&g_scanstate[b], (((unsigned long long)(incl + prefix)) << 2) | 2u);

    if (i < N_NODES) {
        int o = prefix + incl - v;   // exclusive
        g_off[i] = o;
        g_cur[i] = o;
    }
}

// e = lrelu(ssrc[s]+sdst[d]); ex = exp(e - M); scatter (ex, src) into CSR slot
__global__ void k_edge_fused() {
    int i = blockIdx.x * blockDim.x + threadIdx.x;
    if (i >= N_EDGES) return;
    float M = g_maxs[0] + g_maxs[1];
    int2 sd = g_sd[i];
    float x = g_ssrc[sd.x] + g_sdst[sd.y];
    float e = x > 0.f ? x : NEG_SLOPE * x;
    float ex = __expf(e - M);
    int pos = atomicAdd(&g_cur[sd.y], 1);
    g_edge[pos] = make_float2(ex, __int_as_float(sd.x));
}

// warp per node, quarter-warp per edge, 8 edges in flight per iteration
__global__ void k_aggregate(float* __restrict__ out) {
    int w    = (blockIdx.x * blockDim.x + threadIdx.x) >> 5;
    int lane = threadIdx.x & 31;
    if (w >= N_NODES) return;
    int deg  = g_cnt[w];
    int base = g_off[w];
    int q = lane >> 3;
    int r = lane & 7;

    float acc[8];
#pragma unroll
    for (int k = 0; k < 8; k++) acc[k] = 0.f;
    float wsum = 0.f;

    int j = 0;
    for (; j + 8 <= deg; j += 8) {
        float2 e0 = g_edge[base + j + q];
        float2 e1 = g_edge[base + j + 4 + q];
        int s0 = __float_as_int(e0.y);
        int s1 = __float_as_int(e1.y);
        uint4 v0 = *(const uint4*)&g_zh[s0 * OUT_DIM + r * 8];
        uint4 v1 = *(const uint4*)&g_zh[s1 * OUT_DIM + r * 8];
        {
            float2 p0 = __half22float2(*(__half2*)&v0.x);
            float2 p1 = __half22float2(*(__half2*)&v0.y);
            float2 p2 = __half22float2(*(__half2*)&v0.z);
            float2 p3 = __half22float2(*(__half2*)&v0.w);
            acc[0] += e0.x * p0.x; acc[1] += e0.x * p0.y;
            acc[2] += e0.x * p1.x; acc[3] += e0.x * p1.y;
            acc[4] += e0.x * p2.x; acc[5] += e0.x * p2.y;
            acc[6] += e0.x * p3.x; acc[7] += e0.x * p3.y;
        }
        {
            float2 p0 = __half22float2(*(__half2*)&v1.x);
            float2 p1 = __half22float2(*(__half2*)&v1.y);
            float2 p2 = __half22float2(*(__half2*)&v1.z);
            float2 p3 = __half22float2(*(__half2*)&v1.w);
            acc[0] += e1.x * p0.x; acc[1] += e1.x * p0.y;
            acc[2] += e1.x * p1.x; acc[3] += e1.x * p1.y;
            acc[4] += e1.x * p2.x; acc[5] += e1.x * p2.y;
            acc[6] += e1.x * p3.x; acc[7] += e1.x * p3.y;
        }
        wsum += e0.x + e1.x;
    }
    if (j + 4 <= deg) {
        float2 ed = g_edge[base + j + q];
        int   s  = __float_as_int(ed.y);
        uint4 v = *(const uint4*)&g_zh[s * OUT_DIM + r * 8];
        float2 p0 = __half22float2(*(__half2*)&v.x);
        float2 p1 = __half22float2(*(__half2*)&v.y);
        float2 p2 = __half22float2(*(__half2*)&v.z);
        float2 p3 = __half22float2(*(__half2*)&v.w);
        acc[0] += ed.x * p0.x; acc[1] += ed.x * p0.y;
        acc[2] += ed.x * p1.x; acc[3] += ed.x * p1.y;
        acc[4] += ed.x * p2.x; acc[5] += ed.x * p2.y;
        acc[6] += ed.x * p3.x; acc[7] += ed.x * p3.y;
        wsum += ed.x;
        j += 4;
    }
    int rem = deg - j;
    if (q < rem) {
        float2 ed = g_edge[base + j + q];
        int   s  = __float_as_int(ed.y);
        uint4 v = *(const uint4*)&g_zh[s * OUT_DIM + r * 8];
        float2 p0 = __half22float2(*(__half2*)&v.x);
        float2 p1 = __half22float2(*(__half2*)&v.y);
        float2 p2 = __half22float2(*(__half2*)&v.z);
        float2 p3 = __half22float2(*(__half2*)&v.w);
        acc[0] += ed.x * p0.x; acc[1] += ed.x * p0.y;
        acc[2] += ed.x * p1.x; acc[3] += ed.x * p1.y;
        acc[4] += ed.x * p2.x; acc[5] += ed.x * p2.y;
        acc[6] += ed.x * p3.x; acc[7] += ed.x * p3.y;
        wsum += ed.x;
    }
#pragma unroll
    for (int o = 8; o <= 16; o <<= 1) {
#pragma unroll
        for (int k = 0; k < 8; k++)
            acc[k] += __shfl_xor_sync(0xffffffff, acc[k], o);
        wsum += __shfl_xor_sync(0xffffffff, wsum, o);
    }
    if (q == 0) {
        float inv = wsum > 0.f ? 1.f / wsum : 0.f;
        *(float4*)&out[w * OUT_DIM + r * 8] =
            make_float4(acc[0] * inv, acc[1] * inv, acc[2] * inv, acc[3] * inv);
        *(float4*)&out[w * OUT_DIM + r * 8 + 4] =
            make_float4(acc[4] * inv, acc[5] * inv, acc[6] * inv, acc[7] * inv);
    }
}

// ---------------- launch --------------------------------------------------------
extern "C" void kernel_launch(void* const* d_in, const int* in_sizes, int n_in,
                              void* d_out, int out_size) {
    const float* h = (const float*)d_in[0];
    const float* W = (const float*)d_in[1];
    const float* a = (const float*)d_in[2];
    const void*  ei = d_in[3];
    float* out = (float*)d_out;

    cudaFuncSetAttribute(k_fat, cudaFuncAttributeMaxDynamicSharedMemorySize, SMEM_TC_TOTAL);

    void* p_cnt = nullptr;
    void* p_maxs = nullptr;
    void* p_scan = nullptr;
    cudaGetSymbolAddress(&p_cnt, g_cnt);
    cudaGetSymbolAddress(&p_maxs, g_maxs);
    cudaGetSymbolAddress(&p_scan, g_scanstate);
    cudaMemsetAsync(p_cnt, 0, N_NODES * sizeof(int));
    cudaMemsetAsync(p_maxs, 0xFF, 2 * sizeof(float));
    cudaMemsetAsync(p_scan, 0, SCAN_NB * sizeof(unsigned long long));

    k_fat<<<NGB + NCB, 256, SMEM_TC_TOTAL>>>(h, W, a, ei);
    k_scan<<<SCAN_NB, SCAN_B>>>();
    k_edge_fused<<<(N_EDGES + 255) / 256, 256>>>();
    k_aggregate<<<(N_NODES * 32 + 255) / 256, 256>>>(out);
}